// round 1
// baseline (speedup 1.0000x reference)
#include <cuda_runtime.h>
#include <cuda_bf16.h>
#include <math.h>

// Problem constants
#define BATCH   4
#define SEQ     2048
#define DMODEL  1024
#define NHEADS  16
#define DK      64
#define LORA_R  8
#define MTOT    (BATCH * SEQ)       // 8192
#define SCALING 2.0f
#define SM_SCALE 0.125f             // 1/sqrt(64)

// ---------------- scratch (device globals; no allocations allowed) ----------
__device__ float g_t[3 * MTOT * LORA_R];        // lora down: [w][m][r]
__device__ float g_q[MTOT * DMODEL];
__device__ float g_k[MTOT * DMODEL];
__device__ float g_v[MTOT * DMODEL];
__device__ float g_attn[MTOT * DMODEL];

// ---------------- kernel 1: LoRA down projections t = x @ a (3 at once) -----
__global__ void lora_down_kernel(const float* __restrict__ x,
                                 const float* __restrict__ aq,
                                 const float* __restrict__ ak,
                                 const float* __restrict__ av) {
    __shared__ float xs[32][33];
    __shared__ float as[3][32][LORA_R];
    const int tid = threadIdx.x;
    const int row = tid >> 3;        // 0..31
    const int r   = tid & 7;         // 0..7
    const int m0  = blockIdx.x * 32;

    float acc0 = 0.f, acc1 = 0.f, acc2 = 0.f;
    for (int k0 = 0; k0 < DMODEL; k0 += 32) {
        #pragma unroll
        for (int idx = tid; idx < 32 * 32; idx += 256) {
            int rr = idx >> 5, kk = idx & 31;
            xs[rr][kk] = x[(size_t)(m0 + rr) * DMODEL + k0 + kk];
        }
        for (int idx = tid; idx < 3 * 32 * LORA_R; idx += 256) {
            int w = idx >> 8, rem = idx & 255;
            int kk = rem >> 3, rj = rem & 7;
            const float* a = (w == 0) ? aq : ((w == 1) ? ak : av);
            as[w][kk][rj] = a[(size_t)(k0 + kk) * LORA_R + rj];
        }
        __syncthreads();
        #pragma unroll
        for (int kk = 0; kk < 32; kk++) {
            float xv = xs[row][kk];
            acc0 += xv * as[0][kk][r];
            acc1 += xv * as[1][kk][r];
            acc2 += xv * as[2][kk][r];
        }
        __syncthreads();
    }
    const int m = m0 + row;
    g_t[0 * MTOT * LORA_R + m * LORA_R + r] = acc0;
    g_t[1 * MTOT * LORA_R + m * LORA_R + r] = acc1;
    g_t[2 * MTOT * LORA_R + m * LORA_R + r] = acc2;
}

// ---------------- kernel 2: tiled GEMM + bias + optional LoRA epilogue ------
// out[m,n] = sum_k A[m,k]*W[k,n] + bias[n] + 2 * sum_r t[m,r]*u[r,n]
// BM=BN=64, BK=16, 256 threads, 4x4 per thread.
__global__ void gemm_bias_lora_kernel(const float* __restrict__ A,
                                      const float* __restrict__ W,
                                      const float* __restrict__ bias,
                                      const float* __restrict__ t,   // may be null
                                      const float* __restrict__ u,   // may be null
                                      float* __restrict__ out) {
    __shared__ __align__(16) float As[16][68];   // [k][m], padded
    __shared__ __align__(16) float Bs[16][64];   // [k][n]
    __shared__ __align__(16) float Us[LORA_R][64];

    const int tid = threadIdx.x;
    const int tx = tid & 15, ty = tid >> 4;
    const int n0 = blockIdx.x * 64;
    const int m0 = blockIdx.y * 64;

    if (u != nullptr) {
        for (int idx = tid; idx < LORA_R * 64; idx += 256) {
            int r = idx >> 6, n = idx & 63;
            Us[r][n] = u[(size_t)r * DMODEL + n0 + n];
        }
    }

    float acc[4][4] = {};
    const int lm = tid >> 2;         // 0..63 (A row)
    const int lk = tid & 3;          // 0..3  (A k-quad)

    for (int k0 = 0; k0 < DMODEL; k0 += 16) {
        float4 av = *(const float4*)&A[(size_t)(m0 + lm) * DMODEL + k0 + lk * 4];
        As[lk * 4 + 0][lm] = av.x;
        As[lk * 4 + 1][lm] = av.y;
        As[lk * 4 + 2][lm] = av.z;
        As[lk * 4 + 3][lm] = av.w;
        #pragma unroll
        for (int i = 0; i < 4; i++) {
            int idx = tid + i * 256;
            int kk = idx >> 6, nn = idx & 63;
            Bs[kk][nn] = W[(size_t)(k0 + kk) * DMODEL + n0 + nn];
        }
        __syncthreads();
        #pragma unroll
        for (int kk = 0; kk < 16; kk++) {
            float4 a4 = *(const float4*)&As[kk][ty * 4];
            float4 b4 = *(const float4*)&Bs[kk][tx * 4];
            float aa[4] = {a4.x, a4.y, a4.z, a4.w};
            float bb[4] = {b4.x, b4.y, b4.z, b4.w};
            #pragma unroll
            for (int i = 0; i < 4; i++)
                #pragma unroll
                for (int j = 0; j < 4; j++)
                    acc[i][j] += aa[i] * bb[j];
        }
        __syncthreads();
    }

    #pragma unroll
    for (int i = 0; i < 4; i++) {
        const int m = m0 + ty * 4 + i;
        float trow[LORA_R];
        if (t != nullptr) {
            #pragma unroll
            for (int r = 0; r < LORA_R; r++) trow[r] = t[(size_t)m * LORA_R + r];
        }
        #pragma unroll
        for (int j = 0; j < 4; j++) {
            const int n = n0 + tx * 4 + j;
            float v = acc[i][j] + bias[n];
            if (t != nullptr) {
                float lv = 0.f;
                #pragma unroll
                for (int r = 0; r < LORA_R; r++) lv += trow[r] * Us[r][tx * 4 + j];
                v += SCALING * lv;
            }
            out[(size_t)m * DMODEL + n] = v;
        }
    }
}

// ---------------- kernel 3: flash attention (fp32, online softmax) ----------
// Br=Bc=64, dk=64. Block 256 threads, each thread 4 rows x 4 cols.
#define SSTR 68
extern __shared__ float sm_attn[];

__global__ void attn_kernel() {
    float* Qs = sm_attn;                 // 64 * 68
    float* KVs = sm_attn + 64 * SSTR;    // 64 * 68 (K, then reused for V)
    float* Ps = sm_attn + 2 * 64 * SSTR; // 64 * 68

    const int tid = threadIdx.x;
    const int tx = tid & 15, ty = tid >> 4;
    const int r0 = ty * 4, c0 = tx * 4;
    const int q0 = blockIdx.x * 64;
    const int bh = blockIdx.y;
    const int b = bh >> 4, h = bh & 15;

    const float* qbase = g_q + (size_t)b * SEQ * DMODEL + h * DK;
    const float* kbase = g_k + (size_t)b * SEQ * DMODEL + h * DK;
    const float* vbase = g_v + (size_t)b * SEQ * DMODEL + h * DK;

    // load Q tile (scale folded)
    #pragma unroll
    for (int idx = tid; idx < 64 * 16; idx += 256) {
        int row = idx >> 4, d4 = (idx & 15) << 2;
        float4 v4 = *(const float4*)&qbase[(size_t)(q0 + row) * DMODEL + d4];
        v4.x *= SM_SCALE; v4.y *= SM_SCALE; v4.z *= SM_SCALE; v4.w *= SM_SCALE;
        *(float4*)&Qs[row * SSTR + d4] = v4;
    }

    float mi[4], li[4], o[4][4];
    #pragma unroll
    for (int i = 0; i < 4; i++) {
        mi[i] = -1e30f; li[i] = 0.f;
        #pragma unroll
        for (int j = 0; j < 4; j++) o[i][j] = 0.f;
    }
    __syncthreads();

    for (int kv0 = 0; kv0 < SEQ; kv0 += 64) {
        // load K tile
        #pragma unroll
        for (int idx = tid; idx < 64 * 16; idx += 256) {
            int row = idx >> 4, d4 = (idx & 15) << 2;
            *(float4*)&KVs[row * SSTR + d4] =
                *(const float4*)&kbase[(size_t)(kv0 + row) * DMODEL + d4];
        }
        __syncthreads();

        // S = Q K^T (scaled)
        float s[4][4] = {};
        #pragma unroll
        for (int d = 0; d < DK; d += 4) {
            float4 q4[4], k4[4];
            #pragma unroll
            for (int i = 0; i < 4; i++) q4[i] = *(const float4*)&Qs[(r0 + i) * SSTR + d];
            #pragma unroll
            for (int j = 0; j < 4; j++) k4[j] = *(const float4*)&KVs[(c0 + j) * SSTR + d];
            #pragma unroll
            for (int i = 0; i < 4; i++)
                #pragma unroll
                for (int j = 0; j < 4; j++)
                    s[i][j] += q4[i].x * k4[j].x + q4[i].y * k4[j].y +
                               q4[i].z * k4[j].z + q4[i].w * k4[j].w;
        }

        // online softmax per row (rows owned by 16 tx-threads via shfl over tx)
        #pragma unroll
        for (int i = 0; i < 4; i++) {
            float tmax = fmaxf(fmaxf(s[i][0], s[i][1]), fmaxf(s[i][2], s[i][3]));
            #pragma unroll
            for (int mks = 8; mks >= 1; mks >>= 1)
                tmax = fmaxf(tmax, __shfl_xor_sync(0xffffffffu, tmax, mks));
            float mnew = fmaxf(mi[i], tmax);
            float alpha = __expf(mi[i] - mnew);
            float rs = 0.f;
            #pragma unroll
            for (int j = 0; j < 4; j++) {
                float p = __expf(s[i][j] - mnew);
                s[i][j] = p;
                rs += p;
            }
            #pragma unroll
            for (int mks = 8; mks >= 1; mks >>= 1)
                rs += __shfl_xor_sync(0xffffffffu, rs, mks);
            li[i] = li[i] * alpha + rs;
            mi[i] = mnew;
            #pragma unroll
            for (int j = 0; j < 4; j++) o[i][j] *= alpha;
            #pragma unroll
            for (int j = 0; j < 4; j++) Ps[(r0 + i) * SSTR + c0 + j] = s[i][j];
        }
        __syncthreads();

        // load V tile into KVs (all K reads done)
        #pragma unroll
        for (int idx = tid; idx < 64 * 16; idx += 256) {
            int row = idx >> 4, d4 = (idx & 15) << 2;
            *(float4*)&KVs[row * SSTR + d4] =
                *(const float4*)&vbase[(size_t)(kv0 + row) * DMODEL + d4];
        }
        __syncthreads();

        // O += P V
        #pragma unroll 4
        for (int c = 0; c < 64; c++) {
            float4 v4 = *(const float4*)&KVs[c * SSTR + c0];
            #pragma unroll
            for (int i = 0; i < 4; i++) {
                float p = Ps[(r0 + i) * SSTR + c];
                o[i][0] += p * v4.x;
                o[i][1] += p * v4.y;
                o[i][2] += p * v4.z;
                o[i][3] += p * v4.w;
            }
        }
        __syncthreads();
    }

    // normalize + store
    float* abase = g_attn + (size_t)b * SEQ * DMODEL + h * DK;
    #pragma unroll
    for (int i = 0; i < 4; i++) {
        float inv = 1.0f / li[i];
        float4 v4;
        v4.x = o[i][0] * inv; v4.y = o[i][1] * inv;
        v4.z = o[i][2] * inv; v4.w = o[i][3] * inv;
        *(float4*)&abase[(size_t)(q0 + r0 + i) * DMODEL + c0] = v4;
    }
}

// ---------------- launch ----------------------------------------------------
extern "C" void kernel_launch(void* const* d_in, const int* in_sizes, int n_in,
                              void* d_out, int out_size) {
    const float* x   = (const float*)d_in[0];
    const float* w_q = (const float*)d_in[1];
    const float* b_q = (const float*)d_in[2];
    const float* w_k = (const float*)d_in[3];
    const float* b_k = (const float*)d_in[4];
    const float* w_v = (const float*)d_in[5];
    const float* b_v = (const float*)d_in[6];
    const float* w_o = (const float*)d_in[7];
    const float* b_o = (const float*)d_in[8];
    const float* a_q = (const float*)d_in[9];
    const float* u_q = (const float*)d_in[10];
    const float* a_k = (const float*)d_in[11];
    const float* u_k = (const float*)d_in[12];
    const float* a_v = (const float*)d_in[13];
    const float* u_v = (const float*)d_in[14];

    float *t_ptr, *q_ptr, *k_ptr, *v_ptr, *attn_ptr;
    cudaGetSymbolAddress((void**)&t_ptr, g_t);
    cudaGetSymbolAddress((void**)&q_ptr, g_q);
    cudaGetSymbolAddress((void**)&k_ptr, g_k);
    cudaGetSymbolAddress((void**)&v_ptr, g_v);
    cudaGetSymbolAddress((void**)&attn_ptr, g_attn);

    // 1) LoRA down projections
    lora_down_kernel<<<MTOT / 32, 256>>>(x, a_q, a_k, a_v);

    // 2) QKV projections with fused bias + LoRA-up epilogue
    dim3 ggrid(DMODEL / 64, MTOT / 64);
    gemm_bias_lora_kernel<<<ggrid, 256>>>(x, w_q, b_q, t_ptr + 0 * MTOT * LORA_R, u_q, q_ptr);
    gemm_bias_lora_kernel<<<ggrid, 256>>>(x, w_k, b_k, t_ptr + 1 * MTOT * LORA_R, u_k, k_ptr);
    gemm_bias_lora_kernel<<<ggrid, 256>>>(x, w_v, b_v, t_ptr + 2 * MTOT * LORA_R, u_v, v_ptr);

    // 3) attention
    const int attn_smem = 3 * 64 * SSTR * (int)sizeof(float);  // 52224 B
    cudaFuncSetAttribute(attn_kernel, cudaFuncAttributeMaxDynamicSharedMemorySize, attn_smem);
    dim3 agrid(SEQ / 64, BATCH * NHEADS);
    attn_kernel<<<agrid, 256, attn_smem>>>();

    // 4) output projection
    gemm_bias_lora_kernel<<<ggrid, 256>>>(attn_ptr, w_o, b_o, nullptr, nullptr, (float*)d_out);
}

// round 2
// speedup vs baseline: 1.0974x; 1.0974x over previous
#include <cuda_runtime.h>
#include <cuda_bf16.h>
#include <math.h>

// Problem constants
#define BATCH   4
#define SEQ     2048
#define DMODEL  1024
#define NHEADS  16
#define DK      64
#define LORA_R  8
#define MTOT    (BATCH * SEQ)       // 8192
#define SCALING 2.0f
#define SM_SCALE 0.125f             // 1/sqrt(64)

// ---------------- scratch (device globals; no allocations allowed) ----------
__device__ float g_t[3 * MTOT * LORA_R];        // lora down: [w][m][r]
__device__ float g_q[MTOT * DMODEL];
__device__ float g_k[MTOT * DMODEL];
__device__ float g_v[MTOT * DMODEL];
__device__ float g_attn[MTOT * DMODEL];

// ---------------- kernel 1: LoRA down projections t = x @ a (3 at once) -----
__global__ void lora_down_kernel(const float* __restrict__ x,
                                 const float* __restrict__ aq,
                                 const float* __restrict__ ak,
                                 const float* __restrict__ av) {
    __shared__ float xs[32][33];
    __shared__ float as[3][32][LORA_R];
    const int tid = threadIdx.x;
    const int row = tid >> 3;        // 0..31
    const int r   = tid & 7;         // 0..7
    const int m0  = blockIdx.x * 32;

    float acc0 = 0.f, acc1 = 0.f, acc2 = 0.f;
    for (int k0 = 0; k0 < DMODEL; k0 += 32) {
        #pragma unroll
        for (int idx = tid; idx < 32 * 32; idx += 256) {
            int rr = idx >> 5, kk = idx & 31;
            xs[rr][kk] = x[(size_t)(m0 + rr) * DMODEL + k0 + kk];
        }
        for (int idx = tid; idx < 3 * 32 * LORA_R; idx += 256) {
            int w = idx >> 8, rem = idx & 255;
            int kk = rem >> 3, rj = rem & 7;
            const float* a = (w == 0) ? aq : ((w == 1) ? ak : av);
            as[w][kk][rj] = a[(size_t)(k0 + kk) * LORA_R + rj];
        }
        __syncthreads();
        #pragma unroll
        for (int kk = 0; kk < 32; kk++) {
            float xv = xs[row][kk];
            acc0 += xv * as[0][kk][r];
            acc1 += xv * as[1][kk][r];
            acc2 += xv * as[2][kk][r];
        }
        __syncthreads();
    }
    const int m = m0 + row;
    g_t[0 * MTOT * LORA_R + m * LORA_R + r] = acc0;
    g_t[1 * MTOT * LORA_R + m * LORA_R + r] = acc1;
    g_t[2 * MTOT * LORA_R + m * LORA_R + r] = acc2;
}

// ---------------- kernel 2: 128x128 tiled GEMM + bias + LoRA epilogue -------
// out[m,n] = sum_k A[m,k]*W[k,n] + bias[n] + 2 * sum_r t[m,r]*u[r,n]
// BM=BN=128, BK=8, 256 threads, 8x8 per thread (2x2 quads of 4x4).
__global__ __launch_bounds__(256, 2)
void gemm_bias_lora_kernel(const float* __restrict__ A,
                           const float* __restrict__ W,
                           const float* __restrict__ bias,
                           const float* __restrict__ t,   // may be null
                           const float* __restrict__ u,   // may be null
                           float* __restrict__ out) {
    __shared__ __align__(16) float As[2][8][132];   // [buf][k][m]
    __shared__ __align__(16) float Bs[2][8][128];   // [buf][k][n]
    __shared__ __align__(16) float Us[LORA_R][128];

    const int tid = threadIdx.x;
    const int tx = tid & 15, ty = tid >> 4;
    const int n0 = blockIdx.x * 128;
    const int m0 = blockIdx.y * 128;

    if (u != nullptr) {
        #pragma unroll
        for (int p = 0; p < 4; p++) {
            int idx = tid + p * 256;
            int r = idx >> 7, n = idx & 127;
            Us[r][n] = u[(size_t)r * DMODEL + n0 + n];
        }
    }

    // load mappings
    const int arow = tid >> 1;              // 0..127
    const int acol = (tid & 1) * 4;         // 0 or 4
    const int brow = tid >> 5;              // 0..7
    const int bcol = (tid & 31) * 4;        // 0..124

    const float* Aptr = A + (size_t)(m0 + arow) * DMODEL + acol;
    const float* Wptr = W + (size_t)brow * DMODEL + n0 + bcol;

    float4 aS = *(const float4*)Aptr;
    float4 bS = *(const float4*)Wptr;
    As[0][acol + 0][arow] = aS.x;
    As[0][acol + 1][arow] = aS.y;
    As[0][acol + 2][arow] = aS.z;
    As[0][acol + 3][arow] = aS.w;
    *(float4*)&Bs[0][brow][bcol] = bS;
    __syncthreads();

    float acc[8][8] = {};
    int buf = 0;

    for (int k0 = 0; k0 < DMODEL; k0 += 8) {
        const bool next = (k0 + 8) < DMODEL;
        if (next) {
            aS = *(const float4*)(Aptr + k0 + 8);
            bS = *(const float4*)(Wptr + (size_t)(k0 + 8) * DMODEL);
        }
        #pragma unroll
        for (int kk = 0; kk < 8; kk++) {
            float4 a0 = *(const float4*)&As[buf][kk][ty * 4];
            float4 a1 = *(const float4*)&As[buf][kk][64 + ty * 4];
            float4 b0 = *(const float4*)&Bs[buf][kk][tx * 4];
            float4 b1 = *(const float4*)&Bs[buf][kk][64 + tx * 4];
            float aa[8] = {a0.x, a0.y, a0.z, a0.w, a1.x, a1.y, a1.z, a1.w};
            float bb[8] = {b0.x, b0.y, b0.z, b0.w, b1.x, b1.y, b1.z, b1.w};
            #pragma unroll
            for (int i = 0; i < 8; i++)
                #pragma unroll
                for (int j = 0; j < 8; j++)
                    acc[i][j] += aa[i] * bb[j];
        }
        if (next) {
            int nb = buf ^ 1;
            As[nb][acol + 0][arow] = aS.x;
            As[nb][acol + 1][arow] = aS.y;
            As[nb][acol + 2][arow] = aS.z;
            As[nb][acol + 3][arow] = aS.w;
            *(float4*)&Bs[nb][brow][bcol] = bS;
            __syncthreads();
            buf = nb;
        }
    }

    // epilogue: bias + LoRA up
    #pragma unroll
    for (int hi = 0; hi < 2; hi++) {
        #pragma unroll
        for (int i = 0; i < 4; i++) {
            const int m = m0 + hi * 64 + ty * 4 + i;
            float trow[LORA_R];
            if (t != nullptr) {
                #pragma unroll
                for (int r = 0; r < LORA_R; r++) trow[r] = t[(size_t)m * LORA_R + r];
            }
            #pragma unroll
            for (int hj = 0; hj < 2; hj++) {
                const int nloc = hj * 64 + tx * 4;
                float4 v;
                float* vp = &v.x;
                #pragma unroll
                for (int j = 0; j < 4; j++) {
                    float val = acc[hi * 4 + i][hj * 4 + j] + bias[n0 + nloc + j];
                    if (t != nullptr) {
                        float lv = 0.f;
                        #pragma unroll
                        for (int r = 0; r < LORA_R; r++) lv += trow[r] * Us[r][nloc + j];
                        val += SCALING * lv;
                    }
                    vp[j] = val;
                }
                *(float4*)&out[(size_t)m * DMODEL + n0 + nloc] = v;
            }
        }
    }
}

// ---------------- kernel 3: flash attention (fp32, online softmax) ----------
// Br=Bc=64, dk=64. Block 256 threads, each thread 4 rows x 4 cols.
// Separate K/V buffers + register-staged prefetch of next tile.
#define SSTR 68
extern __shared__ float sm_attn[];

__global__ __launch_bounds__(256, 2) void attn_kernel() {
    float* Qs = sm_attn;                 // 64 * 68
    float* Ks = sm_attn + 64 * SSTR;
    float* Vs = sm_attn + 2 * 64 * SSTR;
    float* Ps = sm_attn + 3 * 64 * SSTR;

    const int tid = threadIdx.x;
    const int tx = tid & 15, ty = tid >> 4;
    const int r0 = ty * 4, c0 = tx * 4;
    const int q0 = blockIdx.x * 64;
    const int bh = blockIdx.y;
    const int b = bh >> 4, h = bh & 15;

    const float* qbase = g_q + (size_t)b * SEQ * DMODEL + h * DK;
    const float* kbase = g_k + (size_t)b * SEQ * DMODEL + h * DK;
    const float* vbase = g_v + (size_t)b * SEQ * DMODEL + h * DK;

    // load Q tile (scale folded)
    #pragma unroll
    for (int p = 0; p < 4; p++) {
        int idx = tid + p * 256;
        int row = idx >> 4, d4 = (idx & 15) << 2;
        float4 v4 = *(const float4*)&qbase[(size_t)(q0 + row) * DMODEL + d4];
        v4.x *= SM_SCALE; v4.y *= SM_SCALE; v4.z *= SM_SCALE; v4.w *= SM_SCALE;
        *(float4*)&Qs[row * SSTR + d4] = v4;
    }

    // prefetch tile 0 into registers
    float4 kreg[4], vreg[4];
    #pragma unroll
    for (int p = 0; p < 4; p++) {
        int idx = tid + p * 256;
        int row = idx >> 4, d4 = (idx & 15) << 2;
        kreg[p] = *(const float4*)&kbase[(size_t)row * DMODEL + d4];
        vreg[p] = *(const float4*)&vbase[(size_t)row * DMODEL + d4];
    }

    float mi[4], li[4], o[4][4];
    #pragma unroll
    for (int i = 0; i < 4; i++) {
        mi[i] = -1e30f; li[i] = 0.f;
        #pragma unroll
        for (int j = 0; j < 4; j++) o[i][j] = 0.f;
    }

    for (int kv0 = 0; kv0 < SEQ; kv0 += 64) {
        // commit staged K/V to smem
        #pragma unroll
        for (int p = 0; p < 4; p++) {
            int idx = tid + p * 256;
            int row = idx >> 4, d4 = (idx & 15) << 2;
            *(float4*)&Ks[row * SSTR + d4] = kreg[p];
            *(float4*)&Vs[row * SSTR + d4] = vreg[p];
        }
        __syncthreads();   // K/V (and Q on first iter) visible

        // S = Q K^T (scale pre-folded into Q)
        float s[4][4] = {};
        #pragma unroll
        for (int d = 0; d < DK; d += 4) {
            float4 q4[4], k4[4];
            #pragma unroll
            for (int i = 0; i < 4; i++) q4[i] = *(const float4*)&Qs[(r0 + i) * SSTR + d];
            #pragma unroll
            for (int j = 0; j < 4; j++) k4[j] = *(const float4*)&Ks[(c0 + j) * SSTR + d];
            #pragma unroll
            for (int i = 0; i < 4; i++)
                #pragma unroll
                for (int j = 0; j < 4; j++)
                    s[i][j] += q4[i].x * k4[j].x + q4[i].y * k4[j].y +
                               q4[i].z * k4[j].z + q4[i].w * k4[j].w;
        }

        // online softmax per row (reduce over 16 tx lanes)
        #pragma unroll
        for (int i = 0; i < 4; i++) {
            float tmax = fmaxf(fmaxf(s[i][0], s[i][1]), fmaxf(s[i][2], s[i][3]));
            #pragma unroll
            for (int mks = 8; mks >= 1; mks >>= 1)
                tmax = fmaxf(tmax, __shfl_xor_sync(0xffffffffu, tmax, mks));
            float mnew = fmaxf(mi[i], tmax);
            float alpha = __expf(mi[i] - mnew);
            float rs = 0.f;
            #pragma unroll
            for (int j = 0; j < 4; j++) {
                float p = __expf(s[i][j] - mnew);
                s[i][j] = p;
                rs += p;
            }
            #pragma unroll
            for (int mks = 8; mks >= 1; mks >>= 1)
                rs += __shfl_xor_sync(0xffffffffu, rs, mks);
            li[i] = li[i] * alpha + rs;
            mi[i] = mnew;
            #pragma unroll
            for (int j = 0; j < 4; j++) o[i][j] *= alpha;
            *(float4*)&Ps[(r0 + i) * SSTR + c0] = make_float4(s[i][0], s[i][1], s[i][2], s[i][3]);
        }

        // prefetch next tile while P settles (overlaps with PV below)
        if (kv0 + 64 < SEQ) {
            #pragma unroll
            for (int p = 0; p < 4; p++) {
                int idx = tid + p * 256;
                int row = idx >> 4, d4 = (idx & 15) << 2;
                kreg[p] = *(const float4*)&kbase[(size_t)(kv0 + 64 + row) * DMODEL + d4];
                vreg[p] = *(const float4*)&vbase[(size_t)(kv0 + 64 + row) * DMODEL + d4];
            }
        }
        __syncthreads();   // Ps visible

        // O += P V  (float4 P, 4 V rows per step: 64 FFMA per 8 LDS128)
        #pragma unroll 4
        for (int cq = 0; cq < 16; cq++) {
            float4 v0 = *(const float4*)&Vs[(cq * 4 + 0) * SSTR + c0];
            float4 v1 = *(const float4*)&Vs[(cq * 4 + 1) * SSTR + c0];
            float4 v2 = *(const float4*)&Vs[(cq * 4 + 2) * SSTR + c0];
            float4 v3 = *(const float4*)&Vs[(cq * 4 + 3) * SSTR + c0];
            #pragma unroll
            for (int i = 0; i < 4; i++) {
                float4 p4 = *(const float4*)&Ps[(r0 + i) * SSTR + cq * 4];
                o[i][0] += p4.x * v0.x + p4.y * v1.x + p4.z * v2.x + p4.w * v3.x;
                o[i][1] += p4.x * v0.y + p4.y * v1.y + p4.z * v2.y + p4.w * v3.y;
                o[i][2] += p4.x * v0.z + p4.y * v1.z + p4.z * v2.z + p4.w * v3.z;
                o[i][3] += p4.x * v0.w + p4.y * v1.w + p4.z * v2.w + p4.w * v3.w;
            }
        }
        __syncthreads();   // PV done before next tile overwrites K/V
    }

    // normalize + store
    float* abase = g_attn + (size_t)b * SEQ * DMODEL + h * DK;
    #pragma unroll
    for (int i = 0; i < 4; i++) {
        float inv = 1.0f / li[i];
        float4 v4;
        v4.x = o[i][0] * inv; v4.y = o[i][1] * inv;
        v4.z = o[i][2] * inv; v4.w = o[i][3] * inv;
        *(float4*)&abase[(size_t)(q0 + r0 + i) * DMODEL + c0] = v4;
    }
}

// ---------------- launch ----------------------------------------------------
extern "C" void kernel_launch(void* const* d_in, const int* in_sizes, int n_in,
                              void* d_out, int out_size) {
    const float* x   = (const float*)d_in[0];
    const float* w_q = (const float*)d_in[1];
    const float* b_q = (const float*)d_in[2];
    const float* w_k = (const float*)d_in[3];
    const float* b_k = (const float*)d_in[4];
    const float* w_v = (const float*)d_in[5];
    const float* b_v = (const float*)d_in[6];
    const float* w_o = (const float*)d_in[7];
    const float* b_o = (const float*)d_in[8];
    const float* a_q = (const float*)d_in[9];
    const float* u_q = (const float*)d_in[10];
    const float* a_k = (const float*)d_in[11];
    const float* u_k = (const float*)d_in[12];
    const float* a_v = (const float*)d_in[13];
    const float* u_v = (const float*)d_in[14];

    float *t_ptr, *q_ptr, *k_ptr, *v_ptr, *attn_ptr;
    cudaGetSymbolAddress((void**)&t_ptr, g_t);
    cudaGetSymbolAddress((void**)&q_ptr, g_q);
    cudaGetSymbolAddress((void**)&k_ptr, g_k);
    cudaGetSymbolAddress((void**)&v_ptr, g_v);
    cudaGetSymbolAddress((void**)&attn_ptr, g_attn);

    // 1) LoRA down projections
    lora_down_kernel<<<MTOT / 32, 256>>>(x, a_q, a_k, a_v);

    // 2) QKV projections with fused bias + LoRA-up epilogue
    dim3 ggrid(DMODEL / 128, MTOT / 128);
    gemm_bias_lora_kernel<<<ggrid, 256>>>(x, w_q, b_q, t_ptr + 0 * MTOT * LORA_R, u_q, q_ptr);
    gemm_bias_lora_kernel<<<ggrid, 256>>>(x, w_k, b_k, t_ptr + 1 * MTOT * LORA_R, u_k, k_ptr);
    gemm_bias_lora_kernel<<<ggrid, 256>>>(x, w_v, b_v, t_ptr + 2 * MTOT * LORA_R, u_v, v_ptr);

    // 3) attention
    const int attn_smem = 4 * 64 * SSTR * (int)sizeof(float);  // 69632 B
    cudaFuncSetAttribute(attn_kernel, cudaFuncAttributeMaxDynamicSharedMemorySize, attn_smem);
    dim3 agrid(SEQ / 64, BATCH * NHEADS);
    attn_kernel<<<agrid, 256, attn_smem>>>();

    // 4) output projection
    gemm_bias_lora_kernel<<<ggrid, 256>>>(attn_ptr, w_o, b_o, nullptr, nullptr, (float*)d_out);
}

// round 3
// speedup vs baseline: 2.1273x; 1.9385x over previous
#include <cuda_runtime.h>
#include <cuda_bf16.h>
#include <math.h>

// Problem constants
#define BATCH   4
#define SEQ     2048
#define DMODEL  1024
#define NHEADS  16
#define DK      64
#define LORA_R  8
#define MTOT    (BATCH * SEQ)       // 8192
#define SCALING 2.0f
#define SM_SCALE 0.125f             // 1/sqrt(64)

// ---------------- scratch (device globals; no allocations allowed) ----------
__device__ float g_t[3 * MTOT * LORA_R];        // lora down: [w][m][r]
__device__ float g_q[MTOT * DMODEL];
__device__ float g_k[MTOT * DMODEL];
__device__ float g_v[MTOT * DMODEL];
__device__ float g_attn[MTOT * DMODEL];

// ---------------- tf32 helpers ----------------------------------------------
__device__ __forceinline__ unsigned f2tf(float f) {
    unsigned u;
    asm("cvt.rna.tf32.f32 %0, %1;" : "=r"(u) : "f"(f));
    return u;
}
__device__ __forceinline__ float f2tf_f(float f) { return __uint_as_float(f2tf(f)); }
__device__ __forceinline__ float4 cvt4(float4 v) {
    v.x = f2tf_f(v.x); v.y = f2tf_f(v.y); v.z = f2tf_f(v.z); v.w = f2tf_f(v.w);
    return v;
}
// D += A(16x8 row) * B(8x8 col), tf32 inputs, f32 accum
__device__ __forceinline__ void mma8(float* d, const unsigned* a, unsigned b0, unsigned b1) {
    asm volatile(
        "mma.sync.aligned.m16n8k8.row.col.f32.tf32.tf32.f32 "
        "{%0,%1,%2,%3}, {%4,%5,%6,%7}, {%8,%9}, {%0,%1,%2,%3};\n"
        : "+f"(d[0]), "+f"(d[1]), "+f"(d[2]), "+f"(d[3])
        : "r"(a[0]), "r"(a[1]), "r"(a[2]), "r"(a[3]), "r"(b0), "r"(b1));
}

// ---------------- kernel 1: LoRA down projections t = x @ a (3 at once) -----
__global__ void lora_down_kernel(const float* __restrict__ x,
                                 const float* __restrict__ aq,
                                 const float* __restrict__ ak,
                                 const float* __restrict__ av) {
    __shared__ float xs[32][33];
    __shared__ float as[3][32][LORA_R];
    const int tid = threadIdx.x;
    const int row = tid >> 3;
    const int r   = tid & 7;
    const int m0  = blockIdx.x * 32;

    float acc0 = 0.f, acc1 = 0.f, acc2 = 0.f;
    for (int k0 = 0; k0 < DMODEL; k0 += 32) {
        #pragma unroll
        for (int idx = tid; idx < 32 * 32; idx += 256) {
            int rr = idx >> 5, kk = idx & 31;
            xs[rr][kk] = x[(size_t)(m0 + rr) * DMODEL + k0 + kk];
        }
        for (int idx = tid; idx < 3 * 32 * LORA_R; idx += 256) {
            int w = idx >> 8, rem = idx & 255;
            int kk = rem >> 3, rj = rem & 7;
            const float* a = (w == 0) ? aq : ((w == 1) ? ak : av);
            as[w][kk][rj] = a[(size_t)(k0 + kk) * LORA_R + rj];
        }
        __syncthreads();
        #pragma unroll
        for (int kk = 0; kk < 32; kk++) {
            float xv = xs[row][kk];
            acc0 += xv * as[0][kk][r];
            acc1 += xv * as[1][kk][r];
            acc2 += xv * as[2][kk][r];
        }
        __syncthreads();
    }
    const int m = m0 + row;
    g_t[0 * MTOT * LORA_R + m * LORA_R + r] = acc0;
    g_t[1 * MTOT * LORA_R + m * LORA_R + r] = acc1;
    g_t[2 * MTOT * LORA_R + m * LORA_R + r] = acc2;
}

// ---------------- kernel 2: 128x128 tiled fp32 GEMM + bias + LoRA epilogue --
__global__ __launch_bounds__(256, 2)
void gemm_bias_lora_kernel(const float* __restrict__ A,
                           const float* __restrict__ W,
                           const float* __restrict__ bias,
                           const float* __restrict__ t,   // may be null
                           const float* __restrict__ u,   // may be null
                           float* __restrict__ out) {
    __shared__ __align__(16) float As[2][8][132];
    __shared__ __align__(16) float Bs[2][8][128];
    __shared__ __align__(16) float Us[LORA_R][128];

    const int tid = threadIdx.x;
    const int tx = tid & 15, ty = tid >> 4;
    const int n0 = blockIdx.x * 128;
    const int m0 = blockIdx.y * 128;

    if (u != nullptr) {
        #pragma unroll
        for (int p = 0; p < 4; p++) {
            int idx = tid + p * 256;
            int r = idx >> 7, n = idx & 127;
            Us[r][n] = u[(size_t)r * DMODEL + n0 + n];
        }
    }

    const int arow = tid >> 1;
    const int acol = (tid & 1) * 4;
    const int brow = tid >> 5;
    const int bcol = (tid & 31) * 4;

    const float* Aptr = A + (size_t)(m0 + arow) * DMODEL + acol;
    const float* Wptr = W + (size_t)brow * DMODEL + n0 + bcol;

    float4 aS = *(const float4*)Aptr;
    float4 bS = *(const float4*)Wptr;
    As[0][acol + 0][arow] = aS.x;
    As[0][acol + 1][arow] = aS.y;
    As[0][acol + 2][arow] = aS.z;
    As[0][acol + 3][arow] = aS.w;
    *(float4*)&Bs[0][brow][bcol] = bS;
    __syncthreads();

    float acc[8][8] = {};
    int buf = 0;

    for (int k0 = 0; k0 < DMODEL; k0 += 8) {
        const bool next = (k0 + 8) < DMODEL;
        if (next) {
            aS = *(const float4*)(Aptr + k0 + 8);
            bS = *(const float4*)(Wptr + (size_t)(k0 + 8) * DMODEL);
        }
        #pragma unroll
        for (int kk = 0; kk < 8; kk++) {
            float4 a0 = *(const float4*)&As[buf][kk][ty * 4];
            float4 a1 = *(const float4*)&As[buf][kk][64 + ty * 4];
            float4 b0 = *(const float4*)&Bs[buf][kk][tx * 4];
            float4 b1 = *(const float4*)&Bs[buf][kk][64 + tx * 4];
            float aa[8] = {a0.x, a0.y, a0.z, a0.w, a1.x, a1.y, a1.z, a1.w};
            float bb[8] = {b0.x, b0.y, b0.z, b0.w, b1.x, b1.y, b1.z, b1.w};
            #pragma unroll
            for (int i = 0; i < 8; i++)
                #pragma unroll
                for (int j = 0; j < 8; j++)
                    acc[i][j] += aa[i] * bb[j];
        }
        if (next) {
            int nb = buf ^ 1;
            As[nb][acol + 0][arow] = aS.x;
            As[nb][acol + 1][arow] = aS.y;
            As[nb][acol + 2][arow] = aS.z;
            As[nb][acol + 3][arow] = aS.w;
            *(float4*)&Bs[nb][brow][bcol] = bS;
            __syncthreads();
            buf = nb;
        }
    }

    #pragma unroll
    for (int hi = 0; hi < 2; hi++) {
        #pragma unroll
        for (int i = 0; i < 4; i++) {
            const int m = m0 + hi * 64 + ty * 4 + i;
            float trow[LORA_R];
            if (t != nullptr) {
                #pragma unroll
                for (int r = 0; r < LORA_R; r++) trow[r] = t[(size_t)m * LORA_R + r];
            }
            #pragma unroll
            for (int hj = 0; hj < 2; hj++) {
                const int nloc = hj * 64 + tx * 4;
                float4 v;
                float* vp = &v.x;
                #pragma unroll
                for (int j = 0; j < 4; j++) {
                    float val = acc[hi * 4 + i][hj * 4 + j] + bias[n0 + nloc + j];
                    if (t != nullptr) {
                        float lv = 0.f;
                        #pragma unroll
                        for (int r = 0; r < LORA_R; r++) lv += trow[r] * Us[r][nloc + j];
                        val += SCALING * lv;
                    }
                    vp[j] = val;
                }
                *(float4*)&out[(size_t)m * DMODEL + n0 + nloc] = v;
            }
        }
    }
}

// ---------------- kernel 3: flash attention with tf32 mma.sync --------------
// Br=128 (8 warps x 16 rows), Bc=32, dk=64. 256 threads.
// QK^T and PV on tensor cores (m16n8k8 tf32); softmax warp-local.
#define QSTR 68
#define KSTR 68
#define PSTR 36
extern __shared__ float sm_attn[];

__global__ __launch_bounds__(256, 2) void attn_kernel() {
    float* Qs = sm_attn;                       // 128 x QSTR
    float* Ks = Qs + 128 * QSTR;               // 32 x KSTR
    float* Vs = Ks + 32 * KSTR;                // 32 x KSTR
    float* Ps = Vs + 32 * KSTR;                // 128 x PSTR

    const int tid  = threadIdx.x;
    const int warp = tid >> 5;
    const int lane = tid & 31;
    const int g = lane >> 2;          // 0..7 (row group)
    const int t = lane & 3;           // 0..3
    const int r0 = warp * 16;
    const int q0 = blockIdx.x * 128;
    const int bh = blockIdx.y;
    const int b = bh >> 4, h = bh & 15;

    const float* qbase = g_q + (size_t)b * SEQ * DMODEL + h * DK;
    const float* kbase = g_k + (size_t)b * SEQ * DMODEL + h * DK;
    const float* vbase = g_v + (size_t)b * SEQ * DMODEL + h * DK;

    // load Q tile (scale folded, tf32 rounded)
    #pragma unroll
    for (int p = 0; p < 8; p++) {
        int idx = tid + p * 256;
        int row = idx >> 4, d4 = (idx & 15) << 2;
        float4 v = *(const float4*)&qbase[(size_t)(q0 + row) * DMODEL + d4];
        v.x *= SM_SCALE; v.y *= SM_SCALE; v.z *= SM_SCALE; v.w *= SM_SCALE;
        *(float4*)&Qs[row * QSTR + d4] = cvt4(v);
    }

    // prefetch tile 0 K/V into registers
    float4 kreg[2], vreg[2];
    #pragma unroll
    for (int p = 0; p < 2; p++) {
        int idx = tid + p * 256;
        int row = idx >> 4, d4 = (idx & 15) << 2;
        kreg[p] = *(const float4*)&kbase[(size_t)row * DMODEL + d4];
        vreg[p] = *(const float4*)&vbase[(size_t)row * DMODEL + d4];
    }

    float O[8][4] = {};
    float mi0 = -1e30f, mi1 = -1e30f, li0 = 0.f, li1 = 0.f;

    for (int kv0 = 0; kv0 < SEQ; kv0 += 32) {
        // commit staged K/V (tf32 rounded)
        #pragma unroll
        for (int p = 0; p < 2; p++) {
            int idx = tid + p * 256;
            int row = idx >> 4, d4 = (idx & 15) << 2;
            *(float4*)&Ks[row * KSTR + d4] = cvt4(kreg[p]);
            *(float4*)&Vs[row * KSTR + d4] = cvt4(vreg[p]);
        }
        __syncthreads();

        // ---- S = Q K^T : warp computes 16x32 via 4 n-tiles x 8 k-steps ----
        float S[4][4] = {};
        #pragma unroll
        for (int k0 = 0; k0 < DK; k0 += 8) {
            unsigned a[4];
            a[0] = __float_as_uint(Qs[(r0 + g) * QSTR + k0 + t]);
            a[1] = __float_as_uint(Qs[(r0 + g + 8) * QSTR + k0 + t]);
            a[2] = __float_as_uint(Qs[(r0 + g) * QSTR + k0 + t + 4]);
            a[3] = __float_as_uint(Qs[(r0 + g + 8) * QSTR + k0 + t + 4]);
            #pragma unroll
            for (int nt = 0; nt < 4; nt++) {
                unsigned b0 = __float_as_uint(Ks[(nt * 8 + g) * KSTR + k0 + t]);
                unsigned b1 = __float_as_uint(Ks[(nt * 8 + g) * KSTR + k0 + t + 4]);
                mma8(S[nt], a, b0, b1);
            }
        }

        // ---- online softmax (warp-local; rows g and g+8) ----
        float mx0 = -1e30f, mx1 = -1e30f;
        #pragma unroll
        for (int nt = 0; nt < 4; nt++) {
            mx0 = fmaxf(mx0, fmaxf(S[nt][0], S[nt][1]));
            mx1 = fmaxf(mx1, fmaxf(S[nt][2], S[nt][3]));
        }
        mx0 = fmaxf(mx0, __shfl_xor_sync(0xffffffffu, mx0, 1));
        mx0 = fmaxf(mx0, __shfl_xor_sync(0xffffffffu, mx0, 2));
        mx1 = fmaxf(mx1, __shfl_xor_sync(0xffffffffu, mx1, 1));
        mx1 = fmaxf(mx1, __shfl_xor_sync(0xffffffffu, mx1, 2));
        float mn0 = fmaxf(mi0, mx0), mn1 = fmaxf(mi1, mx1);
        float al0 = __expf(mi0 - mn0), al1 = __expf(mi1 - mn1);
        float sum0 = 0.f, sum1 = 0.f;
        #pragma unroll
        for (int nt = 0; nt < 4; nt++) {
            float p0 = f2tf_f(__expf(S[nt][0] - mn0));
            float p1 = f2tf_f(__expf(S[nt][1] - mn0));
            float p2 = f2tf_f(__expf(S[nt][2] - mn1));
            float p3 = f2tf_f(__expf(S[nt][3] - mn1));
            sum0 += p0 + p1;
            sum1 += p2 + p3;
            *(float2*)&Ps[(r0 + g) * PSTR + nt * 8 + 2 * t]     = make_float2(p0, p1);
            *(float2*)&Ps[(r0 + g + 8) * PSTR + nt * 8 + 2 * t] = make_float2(p2, p3);
        }
        sum0 += __shfl_xor_sync(0xffffffffu, sum0, 1);
        sum0 += __shfl_xor_sync(0xffffffffu, sum0, 2);
        sum1 += __shfl_xor_sync(0xffffffffu, sum1, 1);
        sum1 += __shfl_xor_sync(0xffffffffu, sum1, 2);
        li0 = li0 * al0 + sum0;
        li1 = li1 * al1 + sum1;
        mi0 = mn0; mi1 = mn1;
        #pragma unroll
        for (int nt = 0; nt < 8; nt++) {
            O[nt][0] *= al0; O[nt][1] *= al0;
            O[nt][2] *= al1; O[nt][3] *= al1;
        }

        // prefetch next K/V tile (overlaps with PV)
        if (kv0 + 32 < SEQ) {
            #pragma unroll
            for (int p = 0; p < 2; p++) {
                int idx = tid + p * 256;
                int row = idx >> 4, d4 = (idx & 15) << 2;
                kreg[p] = *(const float4*)&kbase[(size_t)(kv0 + 32 + row) * DMODEL + d4];
                vreg[p] = *(const float4*)&vbase[(size_t)(kv0 + 32 + row) * DMODEL + d4];
            }
        }
        __syncwarp();   // Ps RAW within warp (warp reads only its own rows)

        // ---- O += P V : 4 k-steps x 8 n-tiles ----
        #pragma unroll
        for (int k0 = 0; k0 < 32; k0 += 8) {
            unsigned a[4];
            a[0] = __float_as_uint(Ps[(r0 + g) * PSTR + k0 + t]);
            a[1] = __float_as_uint(Ps[(r0 + g + 8) * PSTR + k0 + t]);
            a[2] = __float_as_uint(Ps[(r0 + g) * PSTR + k0 + t + 4]);
            a[3] = __float_as_uint(Ps[(r0 + g + 8) * PSTR + k0 + t + 4]);
            #pragma unroll
            for (int nt = 0; nt < 8; nt++) {
                unsigned b0 = __float_as_uint(Vs[(k0 + t) * KSTR + nt * 8 + g]);
                unsigned b1 = __float_as_uint(Vs[(k0 + t + 4) * KSTR + nt * 8 + g]);
                mma8(O[nt], a, b0, b1);
            }
        }
        __syncthreads();   // K/V consumed before next commit
    }

    // normalize + store
    float inv0 = 1.0f / li0, inv1 = 1.0f / li1;
    float* abase = g_attn + (size_t)b * SEQ * DMODEL + h * DK;
    const size_t row0 = (size_t)(q0 + r0 + g) * DMODEL;
    const size_t row1 = (size_t)(q0 + r0 + g + 8) * DMODEL;
    #pragma unroll
    for (int nt = 0; nt < 8; nt++) {
        *(float2*)&abase[row0 + nt * 8 + 2 * t] = make_float2(O[nt][0] * inv0, O[nt][1] * inv0);
        *(float2*)&abase[row1 + nt * 8 + 2 * t] = make_float2(O[nt][2] * inv1, O[nt][3] * inv1);
    }
}

// ---------------- launch ----------------------------------------------------
extern "C" void kernel_launch(void* const* d_in, const int* in_sizes, int n_in,
                              void* d_out, int out_size) {
    const float* x   = (const float*)d_in[0];
    const float* w_q = (const float*)d_in[1];
    const float* b_q = (const float*)d_in[2];
    const float* w_k = (const float*)d_in[3];
    const float* b_k = (const float*)d_in[4];
    const float* w_v = (const float*)d_in[5];
    const float* b_v = (const float*)d_in[6];
    const float* w_o = (const float*)d_in[7];
    const float* b_o = (const float*)d_in[8];
    const float* a_q = (const float*)d_in[9];
    const float* u_q = (const float*)d_in[10];
    const float* a_k = (const float*)d_in[11];
    const float* u_k = (const float*)d_in[12];
    const float* a_v = (const float*)d_in[13];
    const float* u_v = (const float*)d_in[14];

    float *t_ptr, *q_ptr, *k_ptr, *v_ptr, *attn_ptr;
    cudaGetSymbolAddress((void**)&t_ptr, g_t);
    cudaGetSymbolAddress((void**)&q_ptr, g_q);
    cudaGetSymbolAddress((void**)&k_ptr, g_k);
    cudaGetSymbolAddress((void**)&v_ptr, g_v);
    cudaGetSymbolAddress((void**)&attn_ptr, g_attn);

    // 1) LoRA down projections
    lora_down_kernel<<<MTOT / 32, 256>>>(x, a_q, a_k, a_v);

    // 2) QKV projections with fused bias + LoRA-up epilogue
    dim3 ggrid(DMODEL / 128, MTOT / 128);
    gemm_bias_lora_kernel<<<ggrid, 256>>>(x, w_q, b_q, t_ptr + 0 * MTOT * LORA_R, u_q, q_ptr);
    gemm_bias_lora_kernel<<<ggrid, 256>>>(x, w_k, b_k, t_ptr + 1 * MTOT * LORA_R, u_k, k_ptr);
    gemm_bias_lora_kernel<<<ggrid, 256>>>(x, w_v, b_v, t_ptr + 2 * MTOT * LORA_R, u_v, v_ptr);

    // 3) attention (tf32 tensor-core flash)
    const int attn_smem = (128 * QSTR + 2 * 32 * KSTR + 128 * PSTR) * (int)sizeof(float); // 70656
    cudaFuncSetAttribute(attn_kernel, cudaFuncAttributeMaxDynamicSharedMemorySize, attn_smem);
    dim3 agrid(SEQ / 128, BATCH * NHEADS);
    attn_kernel<<<agrid, 256, attn_smem>>>();

    // 4) output projection
    gemm_bias_lora_kernel<<<ggrid, 256>>>(attn_ptr, w_o, b_o, nullptr, nullptr, (float*)d_out);
}

// round 4
// speedup vs baseline: 3.3516x; 1.5755x over previous
#include <cuda_runtime.h>
#include <cuda_bf16.h>
#include <math.h>

// Problem constants
#define BATCH   4
#define SEQ     2048
#define DMODEL  1024
#define NHEADS  16
#define DK      64
#define LORA_R  8
#define MTOT    (BATCH * SEQ)       // 8192
#define SCALING 2.0f
#define SM_SCALE 0.125f             // 1/sqrt(64)

// ---------------- scratch (device globals; no allocations allowed) ----------
__device__ float g_t[3 * MTOT * LORA_R];
__device__ float g_q[MTOT * DMODEL];
__device__ float g_k[MTOT * DMODEL];
__device__ float g_v[MTOT * DMODEL];
__device__ float g_attn[MTOT * DMODEL];
__device__ __nv_bfloat16 g_xh[MTOT * DMODEL];
__device__ __nv_bfloat16 g_xl[MTOT * DMODEL];
__device__ __nv_bfloat16 g_wh[4 * DMODEL * DMODEL];
__device__ __nv_bfloat16 g_wl[4 * DMODEL * DMODEL];
__device__ __nv_bfloat16 g_ah[MTOT * DMODEL];
__device__ __nv_bfloat16 g_al[MTOT * DMODEL];

// ---------------- tf32 helpers (attention) ----------------------------------
__device__ __forceinline__ unsigned f2tf(float f) {
    unsigned u;
    asm("cvt.rna.tf32.f32 %0, %1;" : "=r"(u) : "f"(f));
    return u;
}
__device__ __forceinline__ float f2tf_f(float f) { return __uint_as_float(f2tf(f)); }
__device__ __forceinline__ float4 cvt4(float4 v) {
    v.x = f2tf_f(v.x); v.y = f2tf_f(v.y); v.z = f2tf_f(v.z); v.w = f2tf_f(v.w);
    return v;
}
__device__ __forceinline__ void mma8(float* d, const unsigned* a, unsigned b0, unsigned b1) {
    asm volatile(
        "mma.sync.aligned.m16n8k8.row.col.f32.tf32.tf32.f32 "
        "{%0,%1,%2,%3}, {%4,%5,%6,%7}, {%8,%9}, {%0,%1,%2,%3};\n"
        : "+f"(d[0]), "+f"(d[1]), "+f"(d[2]), "+f"(d[3])
        : "r"(a[0]), "r"(a[1]), "r"(a[2]), "r"(a[3]), "r"(b0), "r"(b1));
}
// bf16 m16n8k16 mma, fp32 accum
__device__ __forceinline__ void mma16(float* d, const unsigned* a, unsigned b0, unsigned b1) {
    asm volatile(
        "mma.sync.aligned.m16n8k16.row.col.f32.bf16.bf16.f32 "
        "{%0,%1,%2,%3}, {%4,%5,%6,%7}, {%8,%9}, {%0,%1,%2,%3};\n"
        : "+f"(d[0]), "+f"(d[1]), "+f"(d[2]), "+f"(d[3])
        : "r"(a[0]), "r"(a[1]), "r"(a[2]), "r"(a[3]), "r"(b0), "r"(b1));
}

// ---------------- kernel 0: fp32 -> bf16 hi/lo split ------------------------
__global__ void cvt_hilo_kernel(const float* __restrict__ src,
                                __nv_bfloat16* __restrict__ hi,
                                __nv_bfloat16* __restrict__ lo, int n) {
    int i = (blockIdx.x * blockDim.x + threadIdx.x) * 4;
    if (i >= n) return;
    float4 v = *(const float4*)(src + i);
    __nv_bfloat16 h0 = __float2bfloat16(v.x);
    __nv_bfloat16 h1 = __float2bfloat16(v.y);
    __nv_bfloat16 h2 = __float2bfloat16(v.z);
    __nv_bfloat16 h3 = __float2bfloat16(v.w);
    __nv_bfloat16 l0 = __float2bfloat16(v.x - __bfloat162float(h0));
    __nv_bfloat16 l1 = __float2bfloat16(v.y - __bfloat162float(h1));
    __nv_bfloat16 l2 = __float2bfloat16(v.z - __bfloat162float(h2));
    __nv_bfloat16 l3 = __float2bfloat16(v.w - __bfloat162float(h3));
    *(__nv_bfloat162*)(hi + i)     = __nv_bfloat162(h0, h1);
    *(__nv_bfloat162*)(hi + i + 2) = __nv_bfloat162(h2, h3);
    *(__nv_bfloat162*)(lo + i)     = __nv_bfloat162(l0, l1);
    *(__nv_bfloat162*)(lo + i + 2) = __nv_bfloat162(l2, l3);
}

// ---------------- kernel 1: LoRA down projections ---------------------------
__global__ void lora_down_kernel(const float* __restrict__ x,
                                 const float* __restrict__ aq,
                                 const float* __restrict__ ak,
                                 const float* __restrict__ av) {
    __shared__ float xs[32][33];
    __shared__ float as[3][32][LORA_R];
    const int tid = threadIdx.x;
    const int row = tid >> 3;
    const int r   = tid & 7;
    const int m0  = blockIdx.x * 32;

    float acc0 = 0.f, acc1 = 0.f, acc2 = 0.f;
    for (int k0 = 0; k0 < DMODEL; k0 += 32) {
        #pragma unroll
        for (int idx = tid; idx < 32 * 32; idx += 256) {
            int rr = idx >> 5, kk = idx & 31;
            xs[rr][kk] = x[(size_t)(m0 + rr) * DMODEL + k0 + kk];
        }
        for (int idx = tid; idx < 3 * 32 * LORA_R; idx += 256) {
            int w = idx >> 8, rem = idx & 255;
            int kk = rem >> 3, rj = rem & 7;
            const float* a = (w == 0) ? aq : ((w == 1) ? ak : av);
            as[w][kk][rj] = a[(size_t)(k0 + kk) * LORA_R + rj];
        }
        __syncthreads();
        #pragma unroll
        for (int kk = 0; kk < 32; kk++) {
            float xv = xs[row][kk];
            acc0 += xv * as[0][kk][r];
            acc1 += xv * as[1][kk][r];
            acc2 += xv * as[2][kk][r];
        }
        __syncthreads();
    }
    const int m = m0 + row;
    g_t[0 * MTOT * LORA_R + m * LORA_R + r] = acc0;
    g_t[1 * MTOT * LORA_R + m * LORA_R + r] = acc1;
    g_t[2 * MTOT * LORA_R + m * LORA_R + r] = acc2;
}

// ---------------- kernel 2: bf16x3 tensor-core GEMM + bias + LoRA -----------
// out = A@W + bias + 2*(t@u). A,W given as bf16 hi/lo pairs.
// CTA 128x128, BK=32, 256 threads (8 warps, 2m x 4n), warp tile 64x32.
// SMEM word = packed bf16 k-pair. A rows stride 20 words; B (stored [n][kword])
// stride 20 with word-xor swizzle by (n>>3)&15.
#define AWS 20
#define PLANE (128 * AWS)           // words per [buf][hilo] plane

extern __shared__ unsigned smw[];

__global__ __launch_bounds__(256, 1)
void gemm_bf16x3_kernel(const __nv_bfloat16* __restrict__ Ah,
                        const __nv_bfloat16* __restrict__ Al,
                        const __nv_bfloat16* __restrict__ Wh,
                        const __nv_bfloat16* __restrict__ Wl,
                        const float* __restrict__ bias,
                        const float* __restrict__ t,   // may be null
                        const float* __restrict__ u,   // may be null
                        float* __restrict__ out) {
    unsigned* Asm = smw;                    // 4 planes: [buf][hl]
    unsigned* Bsm = smw + 4 * PLANE;
    float* Us = (float*)(smw + 8 * PLANE);  // [8][128]

    const int tid  = threadIdx.x;
    const int warp = tid >> 5;
    const int lane = tid & 31;
    const int g  = lane >> 2;
    const int tq = lane & 3;
    const int wm = warp >> 2;       // 0..1
    const int wn = warp & 3;        // 0..3
    const int n0 = blockIdx.x * 128;
    const int m0 = blockIdx.y * 128;

    if (u != nullptr) {
        #pragma unroll
        for (int p = 0; p < 4; p++) {
            int idx = tid + p * 256;
            Us[idx] = u[(size_t)(idx >> 7) * DMODEL + n0 + (idx & 127)];
        }
    }

    // ---- staging mappings ----
    const int row_a = tid >> 1;             // 0..127
    const int qa    = tid & 1;              // half-row (16 bf16)
    const int s_b   = tid >> 4;             // 0..15 (k word)
    const int nb    = (tid & 15) * 8;       // n base
    const int pw_b  = s_b ^ ((nb >> 3) & 15);

    const __nv_bfloat16* AhP = Ah + (size_t)(m0 + row_a) * DMODEL + qa * 16;
    const __nv_bfloat16* AlP = Al + (size_t)(m0 + row_a) * DMODEL + qa * 16;
    const __nv_bfloat16* WhP = Wh + (size_t)(2 * s_b) * DMODEL + n0 + nb;
    const __nv_bfloat16* WlP = Wl + (size_t)(2 * s_b) * DMODEL + n0 + nb;

    uint4 sAh0, sAh1, sAl0, sAl1;           // A staging (2 uint4 per hl)
    uint4 sBh0, sBh1, sBl0, sBl1;           // B rows 2s, 2s+1

    // smem store addresses (word indices)
    unsigned* aDst0 = &Asm[0];   // computed per buf below
    (void)aDst0;

    // prologue: load tile 0
    sAh0 = *(const uint4*)(AhP);
    sAh1 = *(const uint4*)(AhP + 8);
    sAl0 = *(const uint4*)(AlP);
    sAl1 = *(const uint4*)(AlP + 8);
    sBh0 = *(const uint4*)(WhP);
    sBh1 = *(const uint4*)(WhP + DMODEL);
    sBl0 = *(const uint4*)(WlP);
    sBl1 = *(const uint4*)(WlP + DMODEL);

    #define STORE_TILE(BUF) do {                                               \
        unsigned* ah = Asm + (BUF) * 2 * PLANE + row_a * AWS + qa * 8;         \
        unsigned* al = ah + PLANE;                                             \
        *(uint4*)(ah)     = sAh0;  *(uint4*)(ah + 4) = sAh1;                   \
        *(uint4*)(al)     = sAl0;  *(uint4*)(al + 4) = sAl1;                   \
        const unsigned short* h0 = (const unsigned short*)&sBh0;               \
        const unsigned short* h1 = (const unsigned short*)&sBh1;               \
        const unsigned short* l0 = (const unsigned short*)&sBl0;               \
        const unsigned short* l1 = (const unsigned short*)&sBl1;               \
        unsigned* bh = Bsm + (BUF) * 2 * PLANE + pw_b;                         \
        unsigned* bl = bh + PLANE;                                             \
        _Pragma("unroll")                                                      \
        for (int j = 0; j < 8; j++) {                                          \
            bh[(nb + j) * AWS] = (unsigned)h0[j] | ((unsigned)h1[j] << 16);    \
            bl[(nb + j) * AWS] = (unsigned)l0[j] | ((unsigned)l1[j] << 16);    \
        }                                                                      \
    } while (0)

    STORE_TILE(0);
    __syncthreads();

    float D[4][4][4] = {};   // [mt][nt][e]

    const int bxor = (wn * 4) & 15;   // base for (n>>3) xor, + nt below
    const int NTILES = DMODEL / 32;   // 32 k-tiles

    for (int tile = 0; tile < NTILES; tile++) {
        const int buf = tile & 1;
        if (tile + 1 < NTILES) {
            const int ko = (tile + 1) * 32;
            sAh0 = *(const uint4*)(AhP + ko);
            sAh1 = *(const uint4*)(AhP + ko + 8);
            sAl0 = *(const uint4*)(AlP + ko);
            sAl1 = *(const uint4*)(AlP + ko + 8);
            sBh0 = *(const uint4*)(WhP + (size_t)ko * DMODEL);
            sBh1 = *(const uint4*)(WhP + (size_t)(ko + 1) * DMODEL);
            sBl0 = *(const uint4*)(WlP + (size_t)ko * DMODEL);
            sBl1 = *(const uint4*)(WlP + (size_t)(ko + 1) * DMODEL);
        }

        const unsigned* Ab = Asm + buf * 2 * PLANE;
        const unsigned* Bb = Bsm + buf * 2 * PLANE;

        #pragma unroll
        for (int ks = 0; ks < 2; ks++) {
            const int wb = ks * 8;
            // B fragments for 4 n-tiles (hi & lo)
            unsigned bh[4][2], bl[4][2];
            #pragma unroll
            for (int nt = 0; nt < 4; nt++) {
                const int n = wn * 32 + nt * 8 + g;
                const int c = (bxor + nt) & 15;
                const unsigned* bp = Bb + n * AWS;
                bh[nt][0] = bp[(wb + tq) ^ c];
                bh[nt][1] = bp[(wb + 4 + tq) ^ c];
                bl[nt][0] = bp[PLANE + ((wb + tq) ^ c)];
                bl[nt][1] = bp[PLANE + ((wb + 4 + tq) ^ c)];
            }
            #pragma unroll
            for (int mt = 0; mt < 4; mt++) {
                const int m = wm * 64 + mt * 16 + g;
                const unsigned* ap = Ab + m * AWS;
                unsigned ah[4], al[4];
                ah[0] = ap[wb + tq];
                ah[1] = ap[8 * AWS + wb + tq];
                ah[2] = ap[wb + 4 + tq];
                ah[3] = ap[8 * AWS + wb + 4 + tq];
                al[0] = ap[PLANE + wb + tq];
                al[1] = ap[PLANE + 8 * AWS + wb + tq];
                al[2] = ap[PLANE + wb + 4 + tq];
                al[3] = ap[PLANE + 8 * AWS + wb + 4 + tq];
                #pragma unroll
                for (int nt = 0; nt < 4; nt++) {
                    mma16(D[mt][nt], ah, bh[nt][0], bh[nt][1]);
                    mma16(D[mt][nt], ah, bl[nt][0], bl[nt][1]);
                    mma16(D[mt][nt], al, bh[nt][0], bh[nt][1]);
                }
            }
        }

        if (tile + 1 < NTILES) {
            STORE_TILE(buf ^ 1);
            __syncthreads();
        }
    }

    // ---- epilogue: bias + LoRA up ----
    #pragma unroll
    for (int mt = 0; mt < 4; mt++) {
        #pragma unroll
        for (int half = 0; half < 2; half++) {
            const int m = m0 + wm * 64 + mt * 16 + g + half * 8;
            float trow[LORA_R];
            if (t != nullptr) {
                float4 t0 = *(const float4*)&t[(size_t)m * LORA_R];
                float4 t1 = *(const float4*)&t[(size_t)m * LORA_R + 4];
                trow[0] = t0.x; trow[1] = t0.y; trow[2] = t0.z; trow[3] = t0.w;
                trow[4] = t1.x; trow[5] = t1.y; trow[6] = t1.z; trow[7] = t1.w;
            }
            #pragma unroll
            for (int nt = 0; nt < 4; nt++) {
                const int ncl = wn * 32 + nt * 8 + 2 * tq;
                float v0 = D[mt][nt][half * 2 + 0] + bias[n0 + ncl];
                float v1 = D[mt][nt][half * 2 + 1] + bias[n0 + ncl + 1];
                if (t != nullptr) {
                    float l0 = 0.f, l1 = 0.f;
                    #pragma unroll
                    for (int r = 0; r < LORA_R; r++) {
                        l0 += trow[r] * Us[r * 128 + ncl];
                        l1 += trow[r] * Us[r * 128 + ncl + 1];
                    }
                    v0 += SCALING * l0;
                    v1 += SCALING * l1;
                }
                *(float2*)&out[(size_t)m * DMODEL + n0 + ncl] = make_float2(v0, v1);
            }
        }
    }
    #undef STORE_TILE
}

// ---------------- kernel 3: flash attention with tf32 mma.sync --------------
#define QSTR 68
#define KSTR 68
#define PSTR 36
extern __shared__ float sm_attn[];

__global__ __launch_bounds__(256, 2) void attn_kernel() {
    float* Qs = sm_attn;
    float* Ks = Qs + 128 * QSTR;
    float* Vs = Ks + 32 * KSTR;
    float* Ps = Vs + 32 * KSTR;

    const int tid  = threadIdx.x;
    const int warp = tid >> 5;
    const int lane = tid & 31;
    const int g = lane >> 2;
    const int t = lane & 3;
    const int r0 = warp * 16;
    const int q0 = blockIdx.x * 128;
    const int bh = blockIdx.y;
    const int b = bh >> 4, h = bh & 15;

    const float* qbase = g_q + (size_t)b * SEQ * DMODEL + h * DK;
    const float* kbase = g_k + (size_t)b * SEQ * DMODEL + h * DK;
    const float* vbase = g_v + (size_t)b * SEQ * DMODEL + h * DK;

    #pragma unroll
    for (int p = 0; p < 8; p++) {
        int idx = tid + p * 256;
        int row = idx >> 4, d4 = (idx & 15) << 2;
        float4 v = *(const float4*)&qbase[(size_t)(q0 + row) * DMODEL + d4];
        v.x *= SM_SCALE; v.y *= SM_SCALE; v.z *= SM_SCALE; v.w *= SM_SCALE;
        *(float4*)&Qs[row * QSTR + d4] = cvt4(v);
    }

    float4 kreg[2], vreg[2];
    #pragma unroll
    for (int p = 0; p < 2; p++) {
        int idx = tid + p * 256;
        int row = idx >> 4, d4 = (idx & 15) << 2;
        kreg[p] = *(const float4*)&kbase[(size_t)row * DMODEL + d4];
        vreg[p] = *(const float4*)&vbase[(size_t)row * DMODEL + d4];
    }

    float O[8][4] = {};
    float mi0 = -1e30f, mi1 = -1e30f, li0 = 0.f, li1 = 0.f;

    for (int kv0 = 0; kv0 < SEQ; kv0 += 32) {
        #pragma unroll
        for (int p = 0; p < 2; p++) {
            int idx = tid + p * 256;
            int row = idx >> 4, d4 = (idx & 15) << 2;
            *(float4*)&Ks[row * KSTR + d4] = cvt4(kreg[p]);
            *(float4*)&Vs[row * KSTR + d4] = cvt4(vreg[p]);
        }
        __syncthreads();

        float S[4][4] = {};
        #pragma unroll
        for (int k0 = 0; k0 < DK; k0 += 8) {
            unsigned a[4];
            a[0] = __float_as_uint(Qs[(r0 + g) * QSTR + k0 + t]);
            a[1] = __float_as_uint(Qs[(r0 + g + 8) * QSTR + k0 + t]);
            a[2] = __float_as_uint(Qs[(r0 + g) * QSTR + k0 + t + 4]);
            a[3] = __float_as_uint(Qs[(r0 + g + 8) * QSTR + k0 + t + 4]);
            #pragma unroll
            for (int nt = 0; nt < 4; nt++) {
                unsigned b0 = __float_as_uint(Ks[(nt * 8 + g) * KSTR + k0 + t]);
                unsigned b1 = __float_as_uint(Ks[(nt * 8 + g) * KSTR + k0 + t + 4]);
                mma8(S[nt], a, b0, b1);
            }
        }

        float mx0 = -1e30f, mx1 = -1e30f;
        #pragma unroll
        for (int nt = 0; nt < 4; nt++) {
            mx0 = fmaxf(mx0, fmaxf(S[nt][0], S[nt][1]));
            mx1 = fmaxf(mx1, fmaxf(S[nt][2], S[nt][3]));
        }
        mx0 = fmaxf(mx0, __shfl_xor_sync(0xffffffffu, mx0, 1));
        mx0 = fmaxf(mx0, __shfl_xor_sync(0xffffffffu, mx0, 2));
        mx1 = fmaxf(mx1, __shfl_xor_sync(0xffffffffu, mx1, 1));
        mx1 = fmaxf(mx1, __shfl_xor_sync(0xffffffffu, mx1, 2));
        float mn0 = fmaxf(mi0, mx0), mn1 = fmaxf(mi1, mx1);
        float al0 = __expf(mi0 - mn0), al1 = __expf(mi1 - mn1);
        float sum0 = 0.f, sum1 = 0.f;
        #pragma unroll
        for (int nt = 0; nt < 4; nt++) {
            float p0 = f2tf_f(__expf(S[nt][0] - mn0));
            float p1 = f2tf_f(__expf(S[nt][1] - mn0));
            float p2 = f2tf_f(__expf(S[nt][2] - mn1));
            float p3 = f2tf_f(__expf(S[nt][3] - mn1));
            sum0 += p0 + p1;
            sum1 += p2 + p3;
            *(float2*)&Ps[(r0 + g) * PSTR + nt * 8 + 2 * t]     = make_float2(p0, p1);
            *(float2*)&Ps[(r0 + g + 8) * PSTR + nt * 8 + 2 * t] = make_float2(p2, p3);
        }
        sum0 += __shfl_xor_sync(0xffffffffu, sum0, 1);
        sum0 += __shfl_xor_sync(0xffffffffu, sum0, 2);
        sum1 += __shfl_xor_sync(0xffffffffu, sum1, 1);
        sum1 += __shfl_xor_sync(0xffffffffu, sum1, 2);
        li0 = li0 * al0 + sum0;
        li1 = li1 * al1 + sum1;
        mi0 = mn0; mi1 = mn1;
        #pragma unroll
        for (int nt = 0; nt < 8; nt++) {
            O[nt][0] *= al0; O[nt][1] *= al0;
            O[nt][2] *= al1; O[nt][3] *= al1;
        }

        if (kv0 + 32 < SEQ) {
            #pragma unroll
            for (int p = 0; p < 2; p++) {
                int idx = tid + p * 256;
                int row = idx >> 4, d4 = (idx & 15) << 2;
                kreg[p] = *(const float4*)&kbase[(size_t)(kv0 + 32 + row) * DMODEL + d4];
                vreg[p] = *(const float4*)&vbase[(size_t)(kv0 + 32 + row) * DMODEL + d4];
            }
        }
        __syncwarp();

        #pragma unroll
        for (int k0 = 0; k0 < 32; k0 += 8) {
            unsigned a[4];
            a[0] = __float_as_uint(Ps[(r0 + g) * PSTR + k0 + t]);
            a[1] = __float_as_uint(Ps[(r0 + g + 8) * PSTR + k0 + t]);
            a[2] = __float_as_uint(Ps[(r0 + g) * PSTR + k0 + t + 4]);
            a[3] = __float_as_uint(Ps[(r0 + g + 8) * PSTR + k0 + t + 4]);
            #pragma unroll
            for (int nt = 0; nt < 8; nt++) {
                unsigned b0 = __float_as_uint(Vs[(k0 + t) * KSTR + nt * 8 + g]);
                unsigned b1 = __float_as_uint(Vs[(k0 + t + 4) * KSTR + nt * 8 + g]);
                mma8(O[nt], a, b0, b1);
            }
        }
        __syncthreads();
    }

    float inv0 = 1.0f / li0, inv1 = 1.0f / li1;
    float* abase = g_attn + (size_t)b * SEQ * DMODEL + h * DK;
    const size_t row0 = (size_t)(q0 + r0 + g) * DMODEL;
    const size_t row1 = (size_t)(q0 + r0 + g + 8) * DMODEL;
    #pragma unroll
    for (int nt = 0; nt < 8; nt++) {
        *(float2*)&abase[row0 + nt * 8 + 2 * t] = make_float2(O[nt][0] * inv0, O[nt][1] * inv0);
        *(float2*)&abase[row1 + nt * 8 + 2 * t] = make_float2(O[nt][2] * inv1, O[nt][3] * inv1);
    }
}

// ---------------- launch ----------------------------------------------------
extern "C" void kernel_launch(void* const* d_in, const int* in_sizes, int n_in,
                              void* d_out, int out_size) {
    const float* x   = (const float*)d_in[0];
    const float* w_q = (const float*)d_in[1];
    const float* b_q = (const float*)d_in[2];
    const float* w_k = (const float*)d_in[3];
    const float* b_k = (const float*)d_in[4];
    const float* w_v = (const float*)d_in[5];
    const float* b_v = (const float*)d_in[6];
    const float* w_o = (const float*)d_in[7];
    const float* b_o = (const float*)d_in[8];
    const float* a_q = (const float*)d_in[9];
    const float* u_q = (const float*)d_in[10];
    const float* a_k = (const float*)d_in[11];
    const float* u_k = (const float*)d_in[12];
    const float* a_v = (const float*)d_in[13];
    const float* u_v = (const float*)d_in[14];

    float *t_ptr, *q_ptr, *k_ptr, *v_ptr, *attn_ptr;
    __nv_bfloat16 *xh, *xl, *wh, *wl, *ah, *al;
    cudaGetSymbolAddress((void**)&t_ptr, g_t);
    cudaGetSymbolAddress((void**)&q_ptr, g_q);
    cudaGetSymbolAddress((void**)&k_ptr, g_k);
    cudaGetSymbolAddress((void**)&v_ptr, g_v);
    cudaGetSymbolAddress((void**)&attn_ptr, g_attn);
    cudaGetSymbolAddress((void**)&xh, g_xh);
    cudaGetSymbolAddress((void**)&xl, g_xl);
    cudaGetSymbolAddress((void**)&wh, g_wh);
    cudaGetSymbolAddress((void**)&wl, g_wl);
    cudaGetSymbolAddress((void**)&ah, g_ah);
    cudaGetSymbolAddress((void**)&al, g_al);

    const int NW = DMODEL * DMODEL;   // 1M

    // 0) hi/lo conversions
    cvt_hilo_kernel<<<(MTOT * DMODEL) / 1024, 256>>>(x, xh, xl, MTOT * DMODEL);
    cvt_hilo_kernel<<<NW / 1024, 256>>>(w_q, wh + 0 * NW, wl + 0 * NW, NW);
    cvt_hilo_kernel<<<NW / 1024, 256>>>(w_k, wh + 1 * NW, wl + 1 * NW, NW);
    cvt_hilo_kernel<<<NW / 1024, 256>>>(w_v, wh + 2 * NW, wl + 2 * NW, NW);
    cvt_hilo_kernel<<<NW / 1024, 256>>>(w_o, wh + 3 * NW, wl + 3 * NW, NW);

    // 1) LoRA down projections
    lora_down_kernel<<<MTOT / 32, 256>>>(x, a_q, a_k, a_v);

    // 2) QKV projections (bf16x3 tensor-core) with bias + LoRA-up epilogue
    const int gsmem = (8 * PLANE) * 4 + LORA_R * 128 * 4;   // 81920 + 4096
    cudaFuncSetAttribute(gemm_bf16x3_kernel, cudaFuncAttributeMaxDynamicSharedMemorySize, gsmem);
    dim3 ggrid(DMODEL / 128, MTOT / 128);
    gemm_bf16x3_kernel<<<ggrid, 256, gsmem>>>(xh, xl, wh + 0 * NW, wl + 0 * NW, b_q,
                                              t_ptr + 0 * MTOT * LORA_R, u_q, q_ptr);
    gemm_bf16x3_kernel<<<ggrid, 256, gsmem>>>(xh, xl, wh + 1 * NW, wl + 1 * NW, b_k,
                                              t_ptr + 1 * MTOT * LORA_R, u_k, k_ptr);
    gemm_bf16x3_kernel<<<ggrid, 256, gsmem>>>(xh, xl, wh + 2 * NW, wl + 2 * NW, b_v,
                                              t_ptr + 2 * MTOT * LORA_R, u_v, v_ptr);

    // 3) attention (tf32 tensor-core flash)
    const int attn_smem = (128 * QSTR + 2 * 32 * KSTR + 128 * PSTR) * (int)sizeof(float);
    cudaFuncSetAttribute(attn_kernel, cudaFuncAttributeMaxDynamicSharedMemorySize, attn_smem);
    dim3 agrid(SEQ / 128, BATCH * NHEADS);
    attn_kernel<<<agrid, 256, attn_smem>>>();

    // 4) output projection
    cvt_hilo_kernel<<<(MTOT * DMODEL) / 1024, 256>>>(attn_ptr, ah, al, MTOT * DMODEL);
    gemm_bf16x3_kernel<<<ggrid, 256, gsmem>>>(ah, al, wh + 3 * NW, wl + 3 * NW, b_o,
                                              nullptr, nullptr, (float*)d_out);
}

// round 6
// speedup vs baseline: 4.5301x; 1.3516x over previous
#include <cuda_runtime.h>
#include <cuda_bf16.h>
#include <cuda_fp16.h>
#include <math.h>
#include <stdint.h>

// Problem constants
#define BATCH   4
#define SEQ     2048
#define DMODEL  1024
#define NHEADS  16
#define DK      64
#define LORA_R  8
#define MTOT    (BATCH * SEQ)       // 8192
#define SCALING 2.0f
#define SM_SCALE 0.125f             // 1/sqrt(64)

// ---------------- scratch (device globals; no allocations allowed) ----------
__device__ float g_t[3 * MTOT * LORA_R];
__device__ __half g_qh[MTOT * DMODEL];            // fp16 Q (pre-scaled by 1/8)
__device__ __half g_kh[MTOT * DMODEL];
__device__ __half g_vh[MTOT * DMODEL];
__device__ __nv_bfloat16 g_xh[MTOT * DMODEL];
__device__ __nv_bfloat16 g_xl[MTOT * DMODEL];
__device__ __nv_bfloat16 g_wh[4 * DMODEL * DMODEL];
__device__ __nv_bfloat16 g_wl[4 * DMODEL * DMODEL];
__device__ __nv_bfloat16 g_ah[MTOT * DMODEL];     // attention out hi
__device__ __nv_bfloat16 g_al[MTOT * DMODEL];     // attention out lo

#define SMEM_SW(off) ((off) ^ (((off) >> 3) & 0x70))

__device__ __forceinline__ uint32_t smem_u32(const void* p) {
    uint32_t a;
    asm("{ .reg .u64 t; cvta.to.shared.u64 t, %1; cvt.u32.u64 %0, t; }" : "=r"(a) : "l"(p));
    return a;
}

// ---------------- mma / ldmatrix helpers -------------------------------------
__device__ __forceinline__ void mma16bf(float* d, const unsigned* a, unsigned b0, unsigned b1) {
    asm volatile(
        "mma.sync.aligned.m16n8k16.row.col.f32.bf16.bf16.f32 "
        "{%0,%1,%2,%3}, {%4,%5,%6,%7}, {%8,%9}, {%0,%1,%2,%3};\n"
        : "+f"(d[0]), "+f"(d[1]), "+f"(d[2]), "+f"(d[3])
        : "r"(a[0]), "r"(a[1]), "r"(a[2]), "r"(a[3]), "r"(b0), "r"(b1));
}
__device__ __forceinline__ void mma16h(float* d, unsigned a0, unsigned a1, unsigned a2,
                                       unsigned a3, unsigned b0, unsigned b1) {
    asm volatile(
        "mma.sync.aligned.m16n8k16.row.col.f32.f16.f16.f32 "
        "{%0,%1,%2,%3}, {%4,%5,%6,%7}, {%8,%9}, {%0,%1,%2,%3};\n"
        : "+f"(d[0]), "+f"(d[1]), "+f"(d[2]), "+f"(d[3])
        : "r"(a0), "r"(a1), "r"(a2), "r"(a3), "r"(b0), "r"(b1));
}
__device__ __forceinline__ void ldsm_x4(unsigned& r0, unsigned& r1, unsigned& r2,
                                        unsigned& r3, uint32_t addr) {
    asm volatile("ldmatrix.sync.aligned.m8n8.x4.shared.b16 {%0,%1,%2,%3}, [%4];"
                 : "=r"(r0), "=r"(r1), "=r"(r2), "=r"(r3) : "r"(addr));
}
__device__ __forceinline__ void ldsm_x4_t(unsigned& r0, unsigned& r1, unsigned& r2,
                                          unsigned& r3, uint32_t addr) {
    asm volatile("ldmatrix.sync.aligned.m8n8.x4.trans.shared.b16 {%0,%1,%2,%3}, [%4];"
                 : "=r"(r0), "=r"(r1), "=r"(r2), "=r"(r3) : "r"(addr));
}

// ---------------- kernel 0a: fp32 -> bf16 hi/lo split ------------------------
__global__ void cvt_hilo_kernel(const float* __restrict__ src,
                                __nv_bfloat16* __restrict__ hi,
                                __nv_bfloat16* __restrict__ lo, int n) {
    int i = (blockIdx.x * blockDim.x + threadIdx.x) * 4;
    if (i >= n) return;
    float4 v = *(const float4*)(src + i);
    __nv_bfloat16 h0 = __float2bfloat16(v.x);
    __nv_bfloat16 h1 = __float2bfloat16(v.y);
    __nv_bfloat16 h2 = __float2bfloat16(v.z);
    __nv_bfloat16 h3 = __float2bfloat16(v.w);
    __nv_bfloat16 l0 = __float2bfloat16(v.x - __bfloat162float(h0));
    __nv_bfloat16 l1 = __float2bfloat16(v.y - __bfloat162float(h1));
    __nv_bfloat16 l2 = __float2bfloat16(v.z - __bfloat162float(h2));
    __nv_bfloat16 l3 = __float2bfloat16(v.w - __bfloat162float(h3));
    *(__nv_bfloat162*)(hi + i)     = __nv_bfloat162(h0, h1);
    *(__nv_bfloat162*)(hi + i + 2) = __nv_bfloat162(h2, h3);
    *(__nv_bfloat162*)(lo + i)     = __nv_bfloat162(l0, l1);
    *(__nv_bfloat162*)(lo + i + 2) = __nv_bfloat162(l2, l3);
}

// ---------------- kernel 1: LoRA down projections ---------------------------
__global__ void lora_down_kernel(const float* __restrict__ x,
                                 const float* __restrict__ aq,
                                 const float* __restrict__ ak,
                                 const float* __restrict__ av) {
    __shared__ float xs[32][33];
    __shared__ float as[3][32][LORA_R];
    const int tid = threadIdx.x;
    const int row = tid >> 3;
    const int r   = tid & 7;
    const int m0  = blockIdx.x * 32;

    float acc0 = 0.f, acc1 = 0.f, acc2 = 0.f;
    for (int k0 = 0; k0 < DMODEL; k0 += 32) {
        #pragma unroll
        for (int idx = tid; idx < 32 * 32; idx += 256) {
            int rr = idx >> 5, kk = idx & 31;
            xs[rr][kk] = x[(size_t)(m0 + rr) * DMODEL + k0 + kk];
        }
        for (int idx = tid; idx < 3 * 32 * LORA_R; idx += 256) {
            int w = idx >> 8, rem = idx & 255;
            int kk = rem >> 3, rj = rem & 7;
            const float* a = (w == 0) ? aq : ((w == 1) ? ak : av);
            as[w][kk][rj] = a[(size_t)(k0 + kk) * LORA_R + rj];
        }
        __syncthreads();
        #pragma unroll
        for (int kk = 0; kk < 32; kk++) {
            float xv = xs[row][kk];
            acc0 += xv * as[0][kk][r];
            acc1 += xv * as[1][kk][r];
            acc2 += xv * as[2][kk][r];
        }
        __syncthreads();
    }
    const int m = m0 + row;
    g_t[0 * MTOT * LORA_R + m * LORA_R + r] = acc0;
    g_t[1 * MTOT * LORA_R + m * LORA_R + r] = acc1;
    g_t[2 * MTOT * LORA_R + m * LORA_R + r] = acc2;
}

// ---------------- kernel 2: bf16x3 tensor-core GEMM + bias + LoRA -----------
// out = A@W + bias + 2*(t@u). A,W as bf16 hi/lo. Output fp32 OR fp16*scale.
#define AWS 20
#define PLANE (128 * AWS)

extern __shared__ unsigned smw[];

__global__ __launch_bounds__(256, 1)
void gemm_bf16x3_kernel(const __nv_bfloat16* __restrict__ Ah,
                        const __nv_bfloat16* __restrict__ Al,
                        const __nv_bfloat16* __restrict__ Wh,
                        const __nv_bfloat16* __restrict__ Wl,
                        const float* __restrict__ bias,
                        const float* __restrict__ t,   // may be null
                        const float* __restrict__ u,   // may be null
                        float* __restrict__ out32,     // may be null
                        __half* __restrict__ out16,    // may be null
                        float oscale) {
    unsigned* Asm = smw;
    unsigned* Bsm = smw + 4 * PLANE;
    float* Us = (float*)(smw + 8 * PLANE);

    const int tid  = threadIdx.x;
    const int warp = tid >> 5;
    const int lane = tid & 31;
    const int g  = lane >> 2;
    const int tq = lane & 3;
    const int wm = warp >> 2;
    const int wn = warp & 3;
    const int n0 = blockIdx.x * 128;
    const int m0 = blockIdx.y * 128;

    if (u != nullptr) {
        #pragma unroll
        for (int p = 0; p < 4; p++) {
            int idx = tid + p * 256;
            Us[idx] = u[(size_t)(idx >> 7) * DMODEL + n0 + (idx & 127)];
        }
    }

    const int row_a = tid >> 1;
    const int qa    = tid & 1;
    const int s_b   = tid >> 4;
    const int nb    = (tid & 15) * 8;
    const int pw_b  = s_b ^ ((nb >> 3) & 15);

    const __nv_bfloat16* AhP = Ah + (size_t)(m0 + row_a) * DMODEL + qa * 16;
    const __nv_bfloat16* AlP = Al + (size_t)(m0 + row_a) * DMODEL + qa * 16;
    const __nv_bfloat16* WhP = Wh + (size_t)(2 * s_b) * DMODEL + n0 + nb;
    const __nv_bfloat16* WlP = Wl + (size_t)(2 * s_b) * DMODEL + n0 + nb;

    uint4 sAh0, sAh1, sAl0, sAl1;
    uint4 sBh0, sBh1, sBl0, sBl1;

    sAh0 = *(const uint4*)(AhP);
    sAh1 = *(const uint4*)(AhP + 8);
    sAl0 = *(const uint4*)(AlP);
    sAl1 = *(const uint4*)(AlP + 8);
    sBh0 = *(const uint4*)(WhP);
    sBh1 = *(const uint4*)(WhP + DMODEL);
    sBl0 = *(const uint4*)(WlP);
    sBl1 = *(const uint4*)(WlP + DMODEL);

    #define STORE_TILE(BUF) do {                                               \
        unsigned* ah = Asm + (BUF) * 2 * PLANE + row_a * AWS + qa * 8;         \
        unsigned* al = ah + PLANE;                                             \
        *(uint4*)(ah)     = sAh0;  *(uint4*)(ah + 4) = sAh1;                   \
        *(uint4*)(al)     = sAl0;  *(uint4*)(al + 4) = sAl1;                   \
        const unsigned short* h0 = (const unsigned short*)&sBh0;               \
        const unsigned short* h1 = (const unsigned short*)&sBh1;               \
        const unsigned short* l0 = (const unsigned short*)&sBl0;               \
        const unsigned short* l1 = (const unsigned short*)&sBl1;               \
        unsigned* bh = Bsm + (BUF) * 2 * PLANE + pw_b;                         \
        unsigned* bl = bh + PLANE;                                             \
        _Pragma("unroll")                                                      \
        for (int j = 0; j < 8; j++) {                                          \
            bh[(nb + j) * AWS] = (unsigned)h0[j] | ((unsigned)h1[j] << 16);    \
            bl[(nb + j) * AWS] = (unsigned)l0[j] | ((unsigned)l1[j] << 16);    \
        }                                                                      \
    } while (0)

    STORE_TILE(0);
    __syncthreads();

    float D[4][4][4] = {};

    const int bxor = (wn * 4) & 15;
    const int NTILES = DMODEL / 32;

    for (int tile = 0; tile < NTILES; tile++) {
        const int buf = tile & 1;
        if (tile + 1 < NTILES) {
            const int ko = (tile + 1) * 32;
            sAh0 = *(const uint4*)(AhP + ko);
            sAh1 = *(const uint4*)(AhP + ko + 8);
            sAl0 = *(const uint4*)(AlP + ko);
            sAl1 = *(const uint4*)(AlP + ko + 8);
            sBh0 = *(const uint4*)(WhP + (size_t)ko * DMODEL);
            sBh1 = *(const uint4*)(WhP + (size_t)(ko + 1) * DMODEL);
            sBl0 = *(const uint4*)(WlP + (size_t)ko * DMODEL);
            sBl1 = *(const uint4*)(WlP + (size_t)(ko + 1) * DMODEL);
        }

        const unsigned* Ab = Asm + buf * 2 * PLANE;
        const unsigned* Bb = Bsm + buf * 2 * PLANE;

        #pragma unroll
        for (int ks = 0; ks < 2; ks++) {
            const int wb = ks * 8;
            unsigned bh[4][2], bl[4][2];
            #pragma unroll
            for (int nt = 0; nt < 4; nt++) {
                const int n = wn * 32 + nt * 8 + g;
                const int c = (bxor + nt) & 15;
                const unsigned* bp = Bb + n * AWS;
                bh[nt][0] = bp[(wb + tq) ^ c];
                bh[nt][1] = bp[(wb + 4 + tq) ^ c];
                bl[nt][0] = bp[PLANE + ((wb + tq) ^ c)];
                bl[nt][1] = bp[PLANE + ((wb + 4 + tq) ^ c)];
            }
            #pragma unroll
            for (int mt = 0; mt < 4; mt++) {
                const int m = wm * 64 + mt * 16 + g;
                const unsigned* ap = Ab + m * AWS;
                unsigned ah[4], al[4];
                ah[0] = ap[wb + tq];
                ah[1] = ap[8 * AWS + wb + tq];
                ah[2] = ap[wb + 4 + tq];
                ah[3] = ap[8 * AWS + wb + 4 + tq];
                al[0] = ap[PLANE + wb + tq];
                al[1] = ap[PLANE + 8 * AWS + wb + tq];
                al[2] = ap[PLANE + wb + 4 + tq];
                al[3] = ap[PLANE + 8 * AWS + wb + 4 + tq];
                #pragma unroll
                for (int nt = 0; nt < 4; nt++) {
                    mma16bf(D[mt][nt], ah, bh[nt][0], bh[nt][1]);
                    mma16bf(D[mt][nt], ah, bl[nt][0], bl[nt][1]);
                    mma16bf(D[mt][nt], al, bh[nt][0], bh[nt][1]);
                }
            }
        }

        if (tile + 1 < NTILES) {
            STORE_TILE(buf ^ 1);
            __syncthreads();
        }
    }

    // ---- epilogue: bias + LoRA up; fp32 or fp16*oscale output ----
    #pragma unroll
    for (int mt = 0; mt < 4; mt++) {
        #pragma unroll
        for (int half_ = 0; half_ < 2; half_++) {
            const int m = m0 + wm * 64 + mt * 16 + g + half_ * 8;
            float trow[LORA_R];
            if (t != nullptr) {
                float4 t0 = *(const float4*)&t[(size_t)m * LORA_R];
                float4 t1 = *(const float4*)&t[(size_t)m * LORA_R + 4];
                trow[0] = t0.x; trow[1] = t0.y; trow[2] = t0.z; trow[3] = t0.w;
                trow[4] = t1.x; trow[5] = t1.y; trow[6] = t1.z; trow[7] = t1.w;
            }
            #pragma unroll
            for (int nt = 0; nt < 4; nt++) {
                const int ncl = wn * 32 + nt * 8 + 2 * tq;
                float v0 = D[mt][nt][half_ * 2 + 0] + bias[n0 + ncl];
                float v1 = D[mt][nt][half_ * 2 + 1] + bias[n0 + ncl + 1];
                if (t != nullptr) {
                    float l0 = 0.f, l1 = 0.f;
                    #pragma unroll
                    for (int r = 0; r < LORA_R; r++) {
                        l0 += trow[r] * Us[r * 128 + ncl];
                        l1 += trow[r] * Us[r * 128 + ncl + 1];
                    }
                    v0 += SCALING * l0;
                    v1 += SCALING * l1;
                }
                if (out16 != nullptr) {
                    __half2 hv = __floats2half2_rn(v0 * oscale, v1 * oscale);
                    *(__half2*)&out16[(size_t)m * DMODEL + n0 + ncl] = hv;
                } else {
                    *(float2*)&out32[(size_t)m * DMODEL + n0 + ncl] = make_float2(v0, v1);
                }
            }
        }
    }
    #undef STORE_TILE
}

// ---------------- kernel 3: flash attention, fp16 m16n8k16 ------------------
// Br=128 (8 warps x 16 rows), Bc=32, dk=64. P kept in registers (FA2).
__global__ __launch_bounds__(256, 2) void attn_kernel() {
    __shared__ __align__(16) __half Qs[128 * 64];   // SW128-swizzled, 128B rows
    __shared__ __align__(16) __half Ks[32 * 64];
    __shared__ __align__(16) __half Vs[32 * 64];

    const int tid  = threadIdx.x;
    const int warp = tid >> 5;
    const int lane = tid & 31;
    const int g = lane >> 2;
    const int t = lane & 3;
    const int r0 = warp * 16;
    const int q0 = blockIdx.x * 128;
    const int bh = blockIdx.y;
    const int b = bh >> 4, h = bh & 15;

    const __half* qbase = g_qh + (size_t)b * SEQ * DMODEL + h * DK;
    const __half* kbase = g_kh + (size_t)b * SEQ * DMODEL + h * DK;
    const __half* vbase = g_vh + (size_t)b * SEQ * DMODEL + h * DK;

    // stage Q (fp16, pre-scaled at GEMM)
    #pragma unroll
    for (int i = 0; i < 4; i++) {
        int idx = tid + i * 256;
        int row = idx >> 3, c8 = idx & 7;
        uint32_t sw = SMEM_SW(row * 128 + c8 * 16);
        *(uint4*)((char*)Qs + sw) = *(const uint4*)(qbase + (size_t)(q0 + row) * DMODEL + c8 * 8);
    }

    // KV prefetch (one uint4 = 8 halves per thread per tile)
    const int srow = tid >> 3, sc8 = tid & 7;
    const uint32_t s_sw = SMEM_SW(srow * 128 + sc8 * 16);
    uint4 kreg = *(const uint4*)(kbase + (size_t)srow * DMODEL + sc8 * 8);
    uint4 vreg = *(const uint4*)(vbase + (size_t)srow * DMODEL + sc8 * 8);

    const uint32_t qb = smem_u32(Qs), kb = smem_u32(Ks), vb = smem_u32(Vs);

    // ldmatrix addresses
    uint32_t qaddr[4];
    #pragma unroll
    for (int ks = 0; ks < 4; ks++)
        qaddr[ks] = qb + SMEM_SW((r0 + (lane & 15)) * 128 + ks * 32 + (lane >> 4) * 16);
    uint32_t kaddr[4][2];
    #pragma unroll
    for (int ks = 0; ks < 4; ks++)
        #pragma unroll
        for (int ntp = 0; ntp < 2; ntp++)
            kaddr[ks][ntp] = kb + SMEM_SW((ntp * 16 + ((lane >> 4) << 3) + (lane & 7)) * 128 +
                                          ((lane >> 3) & 1) * 16 + ks * 32);
    uint32_t vaddr[2][4];
    #pragma unroll
    for (int kp = 0; kp < 2; kp++)
        #pragma unroll
        for (int ntp = 0; ntp < 4; ntp++)
            vaddr[kp][ntp] = vb + SMEM_SW((kp * 16 + ((lane >> 3) & 1) * 8 + (lane & 7)) * 128 +
                                          ntp * 32 + (lane >> 4) * 16);

    float O[8][4] = {};
    float mi0 = -1e30f, mi1 = -1e30f, li0 = 0.f, li1 = 0.f;

    for (int kv0 = 0; kv0 < SEQ; kv0 += 32) {
        *(uint4*)((char*)Ks + s_sw) = kreg;
        *(uint4*)((char*)Vs + s_sw) = vreg;
        __syncthreads();

        // ---- S = Q K^T : 4 k16-steps x 4 n-tiles ----
        float S[4][4] = {};
        #pragma unroll
        for (int ks = 0; ks < 4; ks++) {
            unsigned a0, a1, a2, a3;
            ldsm_x4(a0, a1, a2, a3, qaddr[ks]);
            #pragma unroll
            for (int ntp = 0; ntp < 2; ntp++) {
                unsigned b0, b1, b2, b3;
                ldsm_x4(b0, b1, b2, b3, kaddr[ks][ntp]);
                mma16h(S[ntp * 2],     a0, a1, a2, a3, b0, b1);
                mma16h(S[ntp * 2 + 1], a0, a1, a2, a3, b2, b3);
            }
        }

        // ---- online softmax (rows g, g+8; reduce over 4-lane quad) ----
        float mx0 = -1e30f, mx1 = -1e30f;
        #pragma unroll
        for (int nt = 0; nt < 4; nt++) {
            mx0 = fmaxf(mx0, fmaxf(S[nt][0], S[nt][1]));
            mx1 = fmaxf(mx1, fmaxf(S[nt][2], S[nt][3]));
        }
        mx0 = fmaxf(mx0, __shfl_xor_sync(0xffffffffu, mx0, 1));
        mx0 = fmaxf(mx0, __shfl_xor_sync(0xffffffffu, mx0, 2));
        mx1 = fmaxf(mx1, __shfl_xor_sync(0xffffffffu, mx1, 1));
        mx1 = fmaxf(mx1, __shfl_xor_sync(0xffffffffu, mx1, 2));
        float mn0 = fmaxf(mi0, mx0), mn1 = fmaxf(mi1, mx1);
        float al0 = __expf(mi0 - mn0), al1 = __expf(mi1 - mn1);
        float sum0 = 0.f, sum1 = 0.f;
        unsigned ph[8];   // [nt*2] = half2(p row g), [nt*2+1] = half2(p row g+8)
        #pragma unroll
        for (int nt = 0; nt < 4; nt++) {
            __half2 h01 = __floats2half2_rn(__expf(S[nt][0] - mn0), __expf(S[nt][1] - mn0));
            __half2 h23 = __floats2half2_rn(__expf(S[nt][2] - mn1), __expf(S[nt][3] - mn1));
            ph[nt * 2]     = *(unsigned*)&h01;
            ph[nt * 2 + 1] = *(unsigned*)&h23;
            float2 f01 = __half22float2(h01);
            float2 f23 = __half22float2(h23);
            sum0 += f01.x + f01.y;
            sum1 += f23.x + f23.y;
        }
        sum0 += __shfl_xor_sync(0xffffffffu, sum0, 1);
        sum0 += __shfl_xor_sync(0xffffffffu, sum0, 2);
        sum1 += __shfl_xor_sync(0xffffffffu, sum1, 1);
        sum1 += __shfl_xor_sync(0xffffffffu, sum1, 2);
        li0 = li0 * al0 + sum0;
        li1 = li1 * al1 + sum1;
        mi0 = mn0; mi1 = mn1;
        #pragma unroll
        for (int nt = 0; nt < 8; nt++) {
            O[nt][0] *= al0; O[nt][1] *= al0;
            O[nt][2] *= al1; O[nt][3] *= al1;
        }

        // prefetch next K/V tile (overlaps PV)
        if (kv0 + 32 < SEQ) {
            kreg = *(const uint4*)(kbase + (size_t)(kv0 + 32 + srow) * DMODEL + sc8 * 8);
            vreg = *(const uint4*)(vbase + (size_t)(kv0 + 32 + srow) * DMODEL + sc8 * 8);
        }

        // ---- O += P V : 2 k16-steps x 8 n-tiles; P from registers ----
        #pragma unroll
        for (int kp = 0; kp < 2; kp++) {
            unsigned a0 = ph[kp * 4 + 0], a1 = ph[kp * 4 + 1];
            unsigned a2 = ph[kp * 4 + 2], a3 = ph[kp * 4 + 3];
            #pragma unroll
            for (int ntp = 0; ntp < 4; ntp++) {
                unsigned b0, b1, b2, b3;
                ldsm_x4_t(b0, b1, b2, b3, vaddr[kp][ntp]);
                mma16h(O[ntp * 2],     a0, a1, a2, a3, b0, b1);
                mma16h(O[ntp * 2 + 1], a0, a1, a2, a3, b2, b3);
            }
        }
        __syncthreads();
    }

    // ---- normalize + store directly as bf16 hi/lo (feeds o-projection) ----
    float inv0 = 1.0f / li0, inv1 = 1.0f / li1;
    const size_t row0 = ((size_t)b * SEQ + q0 + r0 + g) * DMODEL + h * DK;
    const size_t row1 = row0 + 8 * DMODEL;
    #pragma unroll
    for (int nt = 0; nt < 8; nt++) {
        const int c = nt * 8 + 2 * t;
        float v0 = O[nt][0] * inv0, v1 = O[nt][1] * inv0;
        float v2 = O[nt][2] * inv1, v3 = O[nt][3] * inv1;
        __nv_bfloat16 h0 = __float2bfloat16(v0), h1 = __float2bfloat16(v1);
        __nv_bfloat16 h2 = __float2bfloat16(v2), h3 = __float2bfloat16(v3);
        *(__nv_bfloat162*)&g_ah[row0 + c] = __nv_bfloat162(h0, h1);
        *(__nv_bfloat162*)&g_ah[row1 + c] = __nv_bfloat162(h2, h3);
        *(__nv_bfloat162*)&g_al[row0 + c] =
            __nv_bfloat162(__float2bfloat16(v0 - __bfloat162float(h0)),
                           __float2bfloat16(v1 - __bfloat162float(h1)));
        *(__nv_bfloat162*)&g_al[row1 + c] =
            __nv_bfloat162(__float2bfloat16(v2 - __bfloat162float(h2)),
                           __float2bfloat16(v3 - __bfloat162float(h3)));
    }
}

// ---------------- launch ----------------------------------------------------
extern "C" void kernel_launch(void* const* d_in, const int* in_sizes, int n_in,
                              void* d_out, int out_size) {
    const float* x   = (const float*)d_in[0];
    const float* w_q = (const float*)d_in[1];
    const float* b_q = (const float*)d_in[2];
    const float* w_k = (const float*)d_in[3];
    const float* b_k = (const float*)d_in[4];
    const float* w_v = (const float*)d_in[5];
    const float* b_v = (const float*)d_in[6];
    const float* w_o = (const float*)d_in[7];
    const float* b_o = (const float*)d_in[8];
    const float* a_q = (const float*)d_in[9];
    const float* u_q = (const float*)d_in[10];
    const float* a_k = (const float*)d_in[11];
    const float* u_k = (const float*)d_in[12];
    const float* a_v = (const float*)d_in[13];
    const float* u_v = (const float*)d_in[14];

    float* t_ptr;
    __half *qh, *kh, *vh;
    __nv_bfloat16 *xh, *xl, *wh, *wl, *ah, *al;
    cudaGetSymbolAddress((void**)&t_ptr, g_t);
    cudaGetSymbolAddress((void**)&qh, g_qh);
    cudaGetSymbolAddress((void**)&kh, g_kh);
    cudaGetSymbolAddress((void**)&vh, g_vh);
    cudaGetSymbolAddress((void**)&xh, g_xh);
    cudaGetSymbolAddress((void**)&xl, g_xl);
    cudaGetSymbolAddress((void**)&wh, g_wh);
    cudaGetSymbolAddress((void**)&wl, g_wl);
    cudaGetSymbolAddress((void**)&ah, g_ah);
    cudaGetSymbolAddress((void**)&al, g_al);

    const int NW = DMODEL * DMODEL;

    // 0) hi/lo conversions
    cvt_hilo_kernel<<<(MTOT * DMODEL) / 1024, 256>>>(x, xh, xl, MTOT * DMODEL);
    cvt_hilo_kernel<<<NW / 1024, 256>>>(w_q, wh + 0 * NW, wl + 0 * NW, NW);
    cvt_hilo_kernel<<<NW / 1024, 256>>>(w_k, wh + 1 * NW, wl + 1 * NW, NW);
    cvt_hilo_kernel<<<NW / 1024, 256>>>(w_v, wh + 2 * NW, wl + 2 * NW, NW);
    cvt_hilo_kernel<<<NW / 1024, 256>>>(w_o, wh + 3 * NW, wl + 3 * NW, NW);

    // 1) LoRA down projections
    lora_down_kernel<<<MTOT / 32, 256>>>(x, a_q, a_k, a_v);

    // 2) QKV projections -> fp16 outputs (Q pre-scaled by 1/8)
    const int gsmem = (8 * PLANE) * 4 + LORA_R * 128 * 4;
    cudaFuncSetAttribute(gemm_bf16x3_kernel, cudaFuncAttributeMaxDynamicSharedMemorySize, gsmem);
    dim3 ggrid(DMODEL / 128, MTOT / 128);
    gemm_bf16x3_kernel<<<ggrid, 256, gsmem>>>(xh, xl, wh + 0 * NW, wl + 0 * NW, b_q,
                                              t_ptr + 0 * MTOT * LORA_R, u_q,
                                              nullptr, qh, SM_SCALE);
    gemm_bf16x3_kernel<<<ggrid, 256, gsmem>>>(xh, xl, wh + 1 * NW, wl + 1 * NW, b_k,
                                              t_ptr + 1 * MTOT * LORA_R, u_k,
                                              nullptr, kh, 1.0f);
    gemm_bf16x3_kernel<<<ggrid, 256, gsmem>>>(xh, xl, wh + 2 * NW, wl + 2 * NW, b_v,
                                              t_ptr + 2 * MTOT * LORA_R, u_v,
                                              nullptr, vh, 1.0f);

    // 3) attention (fp16 tensor-core flash; writes bf16 hi/lo)
    dim3 agrid(SEQ / 128, BATCH * NHEADS);
    attn_kernel<<<agrid, 256>>>();

    // 4) output projection (consumes attention's bf16 hi/lo directly)
    gemm_bf16x3_kernel<<<ggrid, 256, gsmem>>>(ah, al, wh + 3 * NW, wl + 3 * NW, b_o,
                                              nullptr, nullptr,
                                              (float*)d_out, nullptr, 1.0f);
}